// round 14
// baseline (speedup 1.0000x reference)
#include <cuda_runtime.h>
#include <math.h>
#include <stdint.h>

#define BB 8
#define CIN 64
#define COUT 128
#define NPTS 32768
#define RES 32
#define NVOX (RES*RES*RES)
#define GEPS 1e-5f

#define PX 34
#define PY 34
#define PZ 34
#define PVOX (PX*PY*PZ)          // 39304
#define SLK 2048                 // halo slack rows each side (max reach 1191)
#define NTILE 308                // ceil(PVOX/128)

// conv smem partition (floats): KC=32
#define A_STRIDE 36
#define A_BUF (132*A_STRIDE)              // 4752 per buffer
#define B_SLOT 4096                       // one tap: [kp(2)][ni(16)][lane(32)] float4
#define SMEM_FLOATS (2*A_BUF + 4*B_SLOT)  // 25888 floats = 103552 B -> 2 CTAs/SM

// ---------------- scratch (static device globals; no allocation) -------------
__device__ float d_msum[BB*3];
__device__ unsigned d_smaxu[BB];
__device__ float d_normc[BB*3*NPTS];
__device__ __align__(16) float d_gp0[((long)BB*PVOX + 2*SLK)*CIN];   // padded tf32 in (conv1)
__device__ __align__(16) float d_gp1[((long)BB*PVOX + 2*SLK)*COUT];  // conv1 out -> gn1 in-place -> conv2 in
__device__ float d_cnt[BB*NVOX];
__device__ float d_grid2[(long)BB*NVOX*COUT];   // compact conv2 out
__device__ float d_pt[(long)BB*NPTS*COUT];      // point branch
// shuffled weights: [tap][ck][kp(2)][ni(16)][lane(32)] float4
// float4 = { w[n][kb], w[n][kb+4], w[n][kb+8], w[n][kb+12] },
// n = ni*8 + (lane>>2), kb = ck*32 + kp*16 + (lane&3)
__device__ __align__(16) float4 d_wbs1[27*2*2*16*32];   // conv1: NCK=2 (55296)
__device__ __align__(16) float4 d_wbs2[27*4*2*16*32];   // conv2: NCK=4 (110592)
__device__ float d_ptw[CIN*COUT];
__device__ float d_gstats1[BB*8*2];
__device__ float d_cstats2[BB*COUT*2];
__device__ float d_ptstats[BB*8*2];
__device__ float d_A[BB*COUT];
__device__ float d_Bc[BB*COUT];
__device__ float d_ptA[BB*COUT];
__device__ float d_ptB[BB*COUT];

// ---------------- helpers -----------------------------------------------------
__device__ __forceinline__ float rtf32(float x) {
    float r; asm("cvt.rna.tf32.f32 %0, %1;" : "=f"(r) : "f"(x)); return r;
}
__device__ __forceinline__ uint32_t smem_u32(const void* p) {
    uint32_t a;
    asm("{ .reg .u64 t; cvta.to.shared.u64 t, %1; cvt.u32.u64 %0, t; }" : "=r"(a) : "l"(p));
    return a;
}
__device__ __forceinline__ void cpa16(uint32_t dst, const void* src) {
    asm volatile("cp.async.cg.shared.global [%0], [%1], 16;" :: "r"(dst), "l"(src));
}
__device__ __forceinline__ void mma_tf32(float& d0, float& d1, float& d2, float& d3,
                                         uint32_t a0, uint32_t a1, uint32_t a2, uint32_t a3,
                                         uint32_t b0, uint32_t b1) {
    asm volatile(
        "mma.sync.aligned.m16n8k8.row.col.f32.tf32.tf32.f32 "
        "{%0,%1,%2,%3}, {%4,%5,%6,%7}, {%8,%9}, {%0,%1,%2,%3};"
        : "+f"(d0), "+f"(d1), "+f"(d2), "+f"(d3)
        : "r"(a0), "r"(a1), "r"(a2), "r"(a3), "r"(b0), "r"(b1));
}

// ---------------- prep: weights -> kp-packed fragment layout ------------------
__global__ void k_prep(const float* __restrict__ w1, const float* __restrict__ w2,
                       const float* __restrict__ ptw) {
    int e = blockIdx.x * 256 + threadIdx.x;          // covers 110592 float4 entries
    int lane = e & 31, ni = (e >> 5) & 15, kp = (e >> 9) & 1;
    int q = lane >> 2, rr = lane & 3;
    int n = ni*8 + q;
    if (e < 27*2*2*16*32) {                          // conv1, NCK=2
        int ck = (e >> 10) & 1; int tap = e >> 11;
        int kb = ck*32 + kp*16 + rr;
        d_wbs1[e] = make_float4(rtf32(w1[(n*CIN + kb)*27 + tap]),
                                rtf32(w1[(n*CIN + kb + 4)*27 + tap]),
                                rtf32(w1[(n*CIN + kb + 8)*27 + tap]),
                                rtf32(w1[(n*CIN + kb + 12)*27 + tap]));
    }
    if (e < 27*4*2*16*32) {                          // conv2, NCK=4
        int ck = (e >> 10) & 3; int tap = e >> 12;
        int kb = ck*32 + kp*16 + rr;
        d_wbs2[e] = make_float4(rtf32(w2[(n*COUT + kb)*27 + tap]),
                                rtf32(w2[(n*COUT + kb + 4)*27 + tap]),
                                rtf32(w2[(n*COUT + kb + 8)*27 + tap]),
                                rtf32(w2[(n*COUT + kb + 12)*27 + tap]));
    }
    if (e < CIN*COUT) {
        int o = e & 127; int ci = e >> 7;
        d_ptw[e] = ptw[o*CIN + ci];
    }
}

// zero only gp0 INTERIOR (pads are statically zero and never written) + small bufs
__global__ void k_zero0() {
    long i = (long)blockIdx.x * 256 + threadIdx.x;   // BB*NVOX*CIN threads
    int c = i & 63; int v = (int)((i >> 6) & (NVOX-1)); int b = (int)(i >> 21);
    int x = v >> 10, y = (v >> 5) & 31, z = v & 31;
    int pp = ((x+1)*PY + (y+1))*PZ + (z+1);
    d_gp0[((long)SLK + (long)b*PVOX + pp)*CIN + c] = 0.f;
    if (i < BB*NVOX)   d_cnt[i] = 0.f;
    if (i < BB*8*2)    d_gstats1[i] = 0.f;
    if (i < BB*COUT*2) d_cstats2[i] = 0.f;
    if (i < BB*8*2)    d_ptstats[i] = 0.f;
    if (i < BB*3)      d_msum[i] = 0.f;
    if (i < BB)        d_smaxu[i] = 0u;
}

// ---------------- voxelize coords ---------------------------------------------
__global__ void k_mean1(const float* __restrict__ coords) {
    int blk = blockIdx.x;
    int chunk = blk & 15; int d = (blk >> 4) % 3; int b = blk / 48;
    __shared__ float s[256];
    float acc = 0.f;
    int base = (b*3 + d)*NPTS + chunk*2048;
    for (int n = threadIdx.x; n < 2048; n += 256) acc += coords[base + n];
    s[threadIdx.x] = acc; __syncthreads();
    for (int o = 128; o > 0; o >>= 1) {
        if (threadIdx.x < o) s[threadIdx.x] += s[threadIdx.x + o];
        __syncthreads();
    }
    if (threadIdx.x == 0) atomicAdd(&d_msum[b*3 + d], s[0]);
}

__global__ void k_scale1(const float* __restrict__ coords) {
    int blk = blockIdx.x;
    int chunk = blk & 15; int b = blk >> 4;
    float mx = d_msum[b*3]   * (1.f/(float)NPTS);
    float my = d_msum[b*3+1] * (1.f/(float)NPTS);
    float mz = d_msum[b*3+2] * (1.f/(float)NPTS);
    __shared__ float s[256];
    float m = 0.f;
    int n0 = chunk*2048;
    for (int n = threadIdx.x; n < 2048; n += 256) {
        float x = coords[(b*3+0)*NPTS + n0 + n] - mx;
        float y = coords[(b*3+1)*NPTS + n0 + n] - my;
        float z = coords[(b*3+2)*NPTS + n0 + n] - mz;
        m = fmaxf(m, sqrtf(x*x + y*y + z*z));
    }
    s[threadIdx.x] = m; __syncthreads();
    for (int o = 128; o > 0; o >>= 1) {
        if (threadIdx.x < o) s[threadIdx.x] = fmaxf(s[threadIdx.x], s[threadIdx.x + o]);
        __syncthreads();
    }
    if (threadIdx.x == 0) atomicMax(&d_smaxu[b], __float_as_uint(s[0]));
}

__global__ void k_norm(const float* __restrict__ coords) {
    int i = blockIdx.x * 256 + threadIdx.x;
    if (i >= BB*3*NPTS) return;
    int b = i / (3*NPTS); int d = (i / NPTS) % 3;
    float mean = d_msum[b*3 + d] * (1.f/(float)NPTS);
    float scale = __uint_as_float(d_smaxu[b]) * 2.f;
    float t = (coords[i] - mean) / scale + 0.5f;
    d_normc[i] = fminf(fmaxf(t * (float)RES, 0.f), (float)(RES - 1));
}

// ---------------- scatter-mean voxelization into padded grid -----------------
__global__ void k_scatter(const float* __restrict__ feat) {
    int warp = threadIdx.x >> 5, lane = threadIdx.x & 31;
    int p = blockIdx.x * 8 + warp;
    int b = p >> 15, n = p & (NPTS - 1);
    int ix = min(max((int)rintf(d_normc[(b*3+0)*NPTS + n]), 0), RES-1);
    int iy = min(max((int)rintf(d_normc[(b*3+1)*NPTS + n]), 0), RES-1);
    int iz = min(max((int)rintf(d_normc[(b*3+2)*NPTS + n]), 0), RES-1);
    int pp = ((ix+1)*PY + (iy+1))*PZ + (iz+1);
    const float* frow = feat + (long)b*CIN*NPTS + n;
    float v0 = frow[(long)lane * NPTS];
    float v1 = frow[(long)(lane + 32) * NPTS];
    float* row = d_gp0 + ((long)SLK + (long)b*PVOX + pp) * CIN;
    atomicAdd(&row[lane],      v0);
    atomicAdd(&row[lane + 32], v1);
    if (lane == 0) atomicAdd(&d_cnt[b*NVOX + ((ix*RES + iy)*RES + iz)], 1.f);
}

__global__ void k_div() {
    long i = (long)blockIdx.x * 256 + threadIdx.x;
    int c = i & 63; int v = (int)((i >> 6) & (NVOX-1)); int b = (int)(i >> 21);
    int x = v >> 10, y = (v >> 5) & 31, z = v & 31;
    int pp = ((x+1)*PY + (y+1))*PZ + (z+1);
    float cntv = fmaxf(d_cnt[b*NVOX + v], 1.f);
    float* a = d_gp0 + ((long)SLK + (long)b*PVOX + pp) * CIN + c;
    *a = rtf32(*a / cntv);
}

// ---------------- tf32 mma.sync implicit-GEMM 3x3x3 conv ----------------------
// M=128, 256 thr = 8 warps (4m x 2n), 2 CTAs/SM (103.5 KB smem).
// Stage-top holds A(s)+B_t0(s); issue [B_t1][B_t2][A(s+1)+B_t0(s+1)];
// dz waits (2)/(1)/(0 at next top), each with a dz-pass of mma horizon.
// B fragments kp-packed: one LDS.128 per (ni, ks-pair).
// STAGE 0: padded gp1 + fused GN1 group stats; STAGE 1: grid2 + channel stats.
template<int CI, int STAGE>
__global__ void __launch_bounds__(256, 2) k_tconv(const float* __restrict__ bias) {
    extern __shared__ float sm[];
    const int NCK = CI / 32;
    const int NS = 9 * NCK;

    const float*  __restrict__ gin = (STAGE == 0) ? (d_gp0 + (long)SLK*CI)
                                                  : (d_gp1 + (long)SLK*CI);
    const float4* __restrict__ wbs = (STAGE == 0) ? d_wbs1 : d_wbs2;

    int blk = blockIdx.x;                   // BB*NTILE
    int b = blk / NTILE, tile = blk % NTILE;
    long pbase = (long)b * PVOX + tile * 128;

    int tid = threadIdx.x, warp = tid >> 5, lane = tid & 31;
    int wm = warp & 3, wn = warp >> 2;
    uint32_t smb = smem_u32(sm);
    uint32_t aAu[2] = { smb, smb + A_BUF*4 };
    uint32_t aBbase = smb + 2*A_BUF*4;

    float acc[2][8][4];
    #pragma unroll
    for (int mi = 0; mi < 2; mi++)
        #pragma unroll
        for (int ni = 0; ni < 8; ni++)
            #pragma unroll
            for (int j = 0; j < 4; j++) acc[mi][ni][j] = 0.f;

    int q = lane >> 2, rr = lane & 3;
    int aoffs = (wm*32 + q)*A_STRIDE + rr;

    auto issue_A = [&](int s, int abuf) {
        int dxy = s / NCK, ck = s - (s / NCK) * NCK;
        int dxx = dxy / 3 - 1, dyy = dxy % 3 - 1;
        long astart = pbase + dxx * (PY*PZ) + dyy * PZ - 1;
        const float* asrc = gin + astart * CI + ck * 32;
        uint32_t aA = aAu[abuf];
        #pragma unroll
        for (int o2 = 0; o2 < 5; o2++) {
            int i = o2 * 256 + tid;
            if (i < 130*8) {
                int r = i >> 3, seg = i & 7;
                cpa16(aA + (uint32_t)(r*(A_STRIDE*4) + seg*16), asrc + (long)r * CI + seg*4);
            }
        }
    };
    auto issue_B = [&](int s, int dz, int slot) {
        int dxy = s / NCK, ck = s - (s / NCK) * NCK;
        int tap = dxy*3 + dz;
        const float4* bsrc = wbs + (long)(tap * NCK + ck) * 1024;
        uint32_t aB = aBbase + (uint32_t)slot * (B_SLOT*4);
        #pragma unroll
        for (int o2 = 0; o2 < 4; o2++) {
            int i = o2 * 256 + tid;
            cpa16(aB + (uint32_t)(i*16), bsrc + i);
        }
    };
    auto compute = [&](int abuf, int slot, int dz) {
        const uint32_t* sAu = (const uint32_t*)sm + abuf*A_BUF;
        const float4* sB4 = (const float4*)(sm + 2*A_BUF) + slot*1024;
        int abase0 = aoffs + dz*A_STRIDE;
        #pragma unroll
        for (int kp = 0; kp < 2; kp++) {
            uint32_t af[2][2][4];
            #pragma unroll
            for (int mi = 0; mi < 2; mi++)
                #pragma unroll
                for (int kk = 0; kk < 2; kk++) {
                    int abase = abase0 + mi*16*A_STRIDE + (kp*2 + kk)*8;
                    af[mi][kk][0] = sAu[abase];
                    af[mi][kk][1] = sAu[abase + 8*A_STRIDE];
                    af[mi][kk][2] = sAu[abase + 4];
                    af[mi][kk][3] = sAu[abase + 8*A_STRIDE + 4];
                }
            #pragma unroll
            for (int ni = 0; ni < 8; ni++) {
                float4 bv = sB4[(kp*16 + wn*8 + ni)*32 + lane];
                uint32_t b00 = __float_as_uint(bv.x), b01 = __float_as_uint(bv.y);
                uint32_t b10 = __float_as_uint(bv.z), b11 = __float_as_uint(bv.w);
                #pragma unroll
                for (int mi = 0; mi < 2; mi++) {
                    mma_tf32(acc[mi][ni][0], acc[mi][ni][1], acc[mi][ni][2], acc[mi][ni][3],
                             af[mi][0][0], af[mi][0][1], af[mi][0][2], af[mi][0][3], b00, b01);
                    mma_tf32(acc[mi][ni][0], acc[mi][ni][1], acc[mi][ni][2], acc[mi][ni][3],
                             af[mi][1][0], af[mi][1][1], af[mi][1][2], af[mi][1][3], b10, b11);
                }
            }
        }
    };

    issue_A(0, 0);
    issue_B(0, 0, 0);
    asm volatile("cp.async.commit_group;");

    #pragma unroll 1
    for (int s = 0; s < NS; s++) {
        int abuf = s & 1;
        int sl0 = (3*s) & 3, sl1 = (3*s + 1) & 3, sl2 = (3*s + 2) & 3, sl3 = (3*s + 3) & 3;
        asm volatile("cp.async.wait_group %0;" :: "n"(0) : "memory");
        __syncthreads();
        bool more = (s + 1 < NS);
        issue_B(s, 1, sl1); asm volatile("cp.async.commit_group;");
        issue_B(s, 2, sl2); asm volatile("cp.async.commit_group;");
        if (more) {
            issue_A(s + 1, abuf ^ 1);
            issue_B(s + 1, 0, sl3);
            asm volatile("cp.async.commit_group;");
        }
        compute(abuf, sl0, 0);
        if (more) { asm volatile("cp.async.wait_group %0;" :: "n"(2) : "memory"); }
        else      { asm volatile("cp.async.wait_group %0;" :: "n"(1) : "memory"); }
        __syncthreads();
        compute(abuf, sl1, 1);
        if (more) { asm volatile("cp.async.wait_group %0;" :: "n"(1) : "memory"); }
        else      { asm volatile("cp.async.wait_group %0;" :: "n"(0) : "memory"); }
        __syncthreads();
        compute(abuf, sl2, 2);
    }
    __syncthreads();

    // ---- epilogue: discard pad rows, add bias, store, fused stats ----
    if (STAGE == 0) { if (tid < 16) sm[tid] = 0.f; }
    else            { if (tid < 256) sm[tid] = 0.f; }
    __syncthreads();

    int cb = wn*64 + rr*2;
    int prow = tile*128 + wm*32 + q;

    float sg[4] = {0.f, 0.f, 0.f, 0.f}, qg[4] = {0.f, 0.f, 0.f, 0.f};

    #pragma unroll
    for (int mi = 0; mi < 2; mi++) {
        #pragma unroll
        for (int half = 0; half < 2; half++) {
            int pp = prow + mi*16 + half*8;
            int zp = pp % PZ; int rem = pp / PZ; int yp = rem % PY; int xp = rem / PY;
            bool valid = (pp < PVOX) && (xp >= 1 && xp <= 32) && (yp >= 1 && yp <= 32)
                         && (zp >= 1 && zp <= 32);
            if (!valid) continue;
            long ob;
            if (STAGE == 0)
                ob = ((long)SLK + (long)b*PVOX + pp) * COUT;
            else
                ob = ((long)b*NVOX + (((xp-1)*RES + (yp-1))*RES + (zp-1))) * COUT;
            float* gout = (STAGE == 0) ? d_gp1 : d_grid2;
            if (STAGE == 0) {
                #pragma unroll
                for (int ni = 0; ni < 8; ni++) {
                    int col = cb + ni*8;
                    float2 o2;
                    o2.x = acc[mi][ni][half*2]   + bias[col];
                    o2.y = acc[mi][ni][half*2+1] + bias[col+1];
                    *(float2*)&gout[ob + col] = o2;
                    int gl = ni >> 1;
                    sg[gl] += o2.x + o2.y;
                    qg[gl] += o2.x*o2.x + o2.y*o2.y;
                }
            } else {
                #pragma unroll
                for (int ni = 0; ni < 8; ni++) {
                    int col = cb + ni*8;
                    float2 o2;
                    o2.x = acc[mi][ni][half*2]   + bias[col];
                    o2.y = acc[mi][ni][half*2+1] + bias[col+1];
                    *(float2*)&gout[ob + col] = o2;
                    acc[mi][ni][half*2]   = o2.x;
                    acc[mi][ni][half*2+1] = o2.y;
                }
            }
        }
    }

    if (STAGE == 0) {
        #pragma unroll
        for (int g = 0; g < 4; g++) {
            #pragma unroll
            for (int off = 16; off > 0; off >>= 1) {
                sg[g] += __shfl_down_sync(0xffffffffu, sg[g], off);
                qg[g] += __shfl_down_sync(0xffffffffu, qg[g], off);
            }
        }
        if (lane == 0) {
            #pragma unroll
            for (int g = 0; g < 4; g++) {
                atomicAdd(&sm[(wn*4 + g)*2 + 0], sg[g]);
                atomicAdd(&sm[(wn*4 + g)*2 + 1], qg[g]);
            }
        }
        __syncthreads();
        if (tid < 16) atomicAdd(&d_gstats1[b*16 + tid], sm[tid]);
    } else {
        #pragma unroll
        for (int ni = 0; ni < 8; ni++) {
            float sx = 0.f, qx = 0.f, sy = 0.f, qy = 0.f;
            #pragma unroll
            for (int mi = 0; mi < 2; mi++) {
                #pragma unroll
                for (int half = 0; half < 2; half++) {
                    int pp = prow + mi*16 + half*8;
                    int zp = pp % PZ; int rem = pp / PZ; int yp = rem % PY; int xp = rem / PY;
                    bool valid = (pp < PVOX) && (xp >= 1 && xp <= 32) && (yp >= 1 && yp <= 32)
                                 && (zp >= 1 && zp <= 32);
                    if (!valid) continue;
                    float vx = acc[mi][ni][half*2], vy = acc[mi][ni][half*2+1];
                    sx += vx; qx += vx*vx; sy += vy; qy += vy*vy;
                }
            }
            #pragma unroll
            for (int off = 4; off <= 16; off <<= 1) {
                sx += __shfl_xor_sync(0xffffffffu, sx, off);
                qx += __shfl_xor_sync(0xffffffffu, qx, off);
                sy += __shfl_xor_sync(0xffffffffu, sy, off);
                qy += __shfl_xor_sync(0xffffffffu, qy, off);
            }
            if (q == 0) {
                int col = cb + ni*8;
                atomicAdd(&sm[col*2 + 0],       sx);
                atomicAdd(&sm[col*2 + 1],       qx);
                atomicAdd(&sm[(col+1)*2 + 0],   sy);
                atomicAdd(&sm[(col+1)*2 + 1],   qy);
            }
        }
        __syncthreads();
        if (tid < 256) atomicAdd(&d_cstats2[b*256 + tid], sm[tid]);
    }
}

// GN1 normalize + swish + rtf32, IN PLACE on gp1 interior
__global__ void k_gn1(const float* __restrict__ g, const float* __restrict__ bt) {
    long i = (long)blockIdx.x * 256 + threadIdx.x;   // BB*NVOX*COUT
    int c = i & 127; int b = (int)(i >> 22);
    int v = (int)((i >> 7) & (NVOX-1));
    int gr = c >> 4;
    float S = d_gstats1[(b*8 + gr)*2], Q = d_gstats1[(b*8 + gr)*2 + 1];
    const float cnt = (float)NVOX * 16.f;
    float mu = S / cnt; float var = Q / cnt - mu*mu;
    float rs = rsqrtf(var + GEPS);
    int x = v >> 10, yy = (v >> 5) & 31, z = v & 31;
    int pp = ((x+1)*PY + (yy+1))*PZ + (z+1);
    long idx = ((long)SLK + (long)b*PVOX + pp)*COUT + c;
    float y = (d_gp1[idx] - mu) * rs * g[c] + bt[c];
    float sw = y / (1.f + expf(-y));
    d_gp1[idx] = rtf32(sw);
}

// ---------------- SE + fold GN2*SE into per-(b,c) affine ---------------------
__global__ void k_se(const float* __restrict__ w1, const float* __restrict__ b1,
                     const float* __restrict__ w2, const float* __restrict__ b2,
                     const float* __restrict__ gamma, const float* __restrict__ beta) {
    int b = blockIdx.x; int c = threadIdx.x;
    __shared__ float s[128], gmu[8], grs[8], s1[16];
    const float cnt = (float)NVOX;
    if (c < 8) {
        float S = 0.f, Q = 0.f;
        for (int j = 0; j < 16; j++) {
            S += d_cstats2[(b*COUT + c*16 + j)*2 + 0];
            Q += d_cstats2[(b*COUT + c*16 + j)*2 + 1];
        }
        float gc = cnt * 16.f;
        float mu = S / gc; float var = Q / gc - mu*mu;
        gmu[c] = mu; grs[c] = rsqrtf(var + GEPS);
    }
    __syncthreads();
    int gr = c >> 4;
    float mu = gmu[gr], rs = grs[gr];
    float csum = d_cstats2[(b*COUT + c)*2];
    s[c] = (csum / cnt - mu) * rs * gamma[c] + beta[c];
    __syncthreads();
    if (c < 16) {
        float a = b1[c];
        for (int j = 0; j < 128; j++) a += w1[c*128 + j] * s[j];
        s1[c] = fmaxf(a, 0.f);
    }
    __syncthreads();
    float a2 = b2[c];
    for (int j = 0; j < 16; j++) a2 += w2[c*16 + j] * s1[j];
    float se = 1.f / (1.f + expf(-a2));
    float rg = rs * gamma[c];
    d_A [b*COUT + c] = rg * se;
    d_Bc[b*COUT + c] = (beta[c] - mu * rg) * se;
}

// ---------------- point branch 1x1 conv + stats --------------------------------
__global__ void k_pt(const float* __restrict__ feat, const float* __restrict__ ptb) {
    int blk = blockIdx.x;
    int b = blk >> 10, n0 = (blk & 1023) * 32;
    __shared__ float fs[CIN*32];
    __shared__ float so[32*COUT];
    __shared__ float ss[256], sq[256];
    for (int e = threadIdx.x; e < CIN*32; e += 256) {
        int ci = e >> 5, nn = e & 31;
        fs[e] = feat[((long)(b*CIN) + ci)*NPTS + n0 + nn];
    }
    __syncthreads();
    int o = threadIdx.x & 127, h = threadIdx.x >> 7;
    float acc[16];
    float bv = ptb[o];
    #pragma unroll
    for (int j = 0; j < 16; j++) acc[j] = bv;
    for (int ci = 0; ci < CIN; ci++) {
        float w = d_ptw[ci*COUT + o];
        #pragma unroll
        for (int j = 0; j < 16; j++)
            acc[j] = fmaf(w, fs[ci*32 + h*16 + j], acc[j]);
    }
    float s = 0.f, q = 0.f;
    #pragma unroll
    for (int j = 0; j < 16; j++) {
        s += acc[j]; q += acc[j]*acc[j];
        so[(h*16 + j)*COUT + o] = acc[j];
    }
    ss[threadIdx.x] = s; sq[threadIdx.x] = q;
    __syncthreads();
    if (threadIdx.x < 8) {
        float S = 0.f, Q = 0.f;
        for (int j = 0; j < 16; j++) {
            int cc = threadIdx.x*16 + j;
            S += ss[cc] + ss[cc+128]; Q += sq[cc] + sq[cc+128];
        }
        atomicAdd(&d_ptstats[(b*8 + threadIdx.x)*2 + 0], S);
        atomicAdd(&d_ptstats[(b*8 + threadIdx.x)*2 + 1], Q);
    }
    for (int e = threadIdx.x; e < 32*COUT; e += 256) {
        int nn = e >> 7, oo = e & 127;
        d_pt[((long)(b*NPTS) + n0 + nn)*COUT + oo] = so[e];
    }
}

__global__ void k_ptab(const float* __restrict__ g, const float* __restrict__ bt) {
    int i = blockIdx.x * 256 + threadIdx.x;
    if (i >= BB*COUT) return;
    int b = i >> 7, c = i & 127, gr = c >> 4;
    const float cnt = 16.f * (float)NPTS;
    float S = d_ptstats[(b*8 + gr)*2], Q = d_ptstats[(b*8 + gr)*2 + 1];
    float mu = S / cnt, var = Q / cnt - mu*mu, rs = rsqrtf(var + GEPS);
    d_ptA[i] = rs * g[c];
    d_ptB[i] = bt[c] - mu * rs * g[c];
}

// ---------------- trilinear devoxelize + point add -> out (coalesced) ---------
__global__ void k_out(float* __restrict__ out) {
    __shared__ float so[64*132];
    int warp = threadIdx.x >> 5, lane = threadIdx.x & 31;
    int blk = blockIdx.x;
    int b = blk >> 9;
    int n0 = (blk & 511) * 64;

    #pragma unroll 1
    for (int pass = 0; pass < 8; pass++) {
        int pt = pass * 8 + warp;
        int n = n0 + pt;
        float nx = d_normc[(b*3+0)*NPTS + n];
        float ny = d_normc[(b*3+1)*NPTS + n];
        float nz = d_normc[(b*3+2)*NPTS + n];
        int lx = (int)floorf(nx); float fx = nx - (float)lx; int hx = min(lx+1, RES-1);
        int ly = (int)floorf(ny); float fy = ny - (float)ly; int hy = min(ly+1, RES-1);
        int lz = (int)floorf(nz); float fz = nz - (float)lz; int hz = min(lz+1, RES-1);

        float4 acc = make_float4(0.f, 0.f, 0.f, 0.f);
        float sumw = 0.f;
        const float4* gp = (const float4*)d_grid2;
        #pragma unroll
        for (int k = 0; k < 8; k++) {
            int dx = k >> 2, dy = (k >> 1) & 1, dz = k & 1;
            int ix = dx ? hx : lx, iy = dy ? hy : ly, iz = dz ? hz : lz;
            float w = (dx ? fx : 1.f - fx) * (dy ? fy : 1.f - fy) * (dz ? fz : 1.f - fz);
            long row = ((long)(b*NVOX) + (ix*RES + iy)*RES + iz) * (COUT/4);
            float4 v = gp[row + lane];
            acc.x += w*v.x; acc.y += w*v.y; acc.z += w*v.z; acc.w += w*v.w;
            sumw += w;
        }
        float4 a  = ((const float4*)d_A )[b*32 + lane];
        float4 bc = ((const float4*)d_Bc)[b*32 + lane];
        float4 gv;
        gv.x = acc.x*a.x + sumw*bc.x; gv.y = acc.y*a.y + sumw*bc.y;
        gv.z = acc.z*a.z + sumw*bc.z; gv.w = acc.w*a.w + sumw*bc.w;

        float4 pv = ((const float4*)d_pt)[((long)(b*NPTS) + n)*32 + lane];
        float4 pa = ((const float4*)d_ptA)[b*32 + lane];
        float4 pb = ((const float4*)d_ptB)[b*32 + lane];
        float y;
        y = pv.x*pa.x + pb.x; gv.x += y / (1.f + expf(-y));
        y = pv.y*pa.y + pb.y; gv.y += y / (1.f + expf(-y));
        y = pv.z*pa.z + pb.z; gv.z += y / (1.f + expf(-y));
        y = pv.w*pa.w + pb.w; gv.w += y / (1.f + expf(-y));

        ((float4*)(so + pt*132))[lane] = gv;
    }
    __syncthreads();
    for (int e = threadIdx.x; e < 64*128; e += 256) {
        int c = e >> 6, n = e & 63;
        out[((long)(b*COUT) + c)*NPTS + n0 + n] = so[n*132 + c];
    }
}

// ---------------- launch --------------------------------------------------------
extern "C" void kernel_launch(void* const* d_in, const int* in_sizes, int n_in,
                              void* d_out, int out_size) {
    const float* features = (const float*)d_in[0];
    const float* coords   = (const float*)d_in[1];
    const float* conv1_w  = (const float*)d_in[2];
    const float* conv1_b  = (const float*)d_in[3];
    const float* gn1_g    = (const float*)d_in[4];
    const float* gn1_b    = (const float*)d_in[5];
    const float* conv2_w  = (const float*)d_in[6];
    const float* conv2_b  = (const float*)d_in[7];
    const float* gn2_g    = (const float*)d_in[8];
    const float* gn2_b    = (const float*)d_in[9];
    const float* se_w1    = (const float*)d_in[10];
    const float* se_b1    = (const float*)d_in[11];
    const float* se_w2    = (const float*)d_in[12];
    const float* se_b2    = (const float*)d_in[13];
    const float* pt_w     = (const float*)d_in[14];
    const float* pt_b     = (const float*)d_in[15];
    const float* ptgn_g   = (const float*)d_in[16];
    const float* ptgn_b   = (const float*)d_in[17];
    float* out = (float*)d_out;

    const int SMEM_B = SMEM_FLOATS * 4;    // 103552
    cudaFuncSetAttribute(k_tconv<CIN,0>,  cudaFuncAttributeMaxDynamicSharedMemorySize, SMEM_B);
    cudaFuncSetAttribute(k_tconv<COUT,1>, cudaFuncAttributeMaxDynamicSharedMemorySize, SMEM_B);

    k_prep<<<(27*4*2*16*32 + 255)/256, 256>>>(conv1_w, conv2_w, pt_w);
    k_zero0<<<(int)(((long)BB*NVOX*CIN)/256), 256>>>();
    k_mean1<<<BB*3*16, 256>>>(coords);
    k_scale1<<<BB*16, 256>>>(coords);
    k_norm<<<(BB*3*NPTS + 255)/256, 256>>>(coords);
    k_scatter<<<BB*NPTS/8, 256>>>(features);
    k_div<<<(BB*NVOX*CIN)/256, 256>>>();
    k_tconv<CIN,0><<<BB*NTILE, 256, SMEM_B>>>(conv1_b);
    k_gn1<<<(BB*NVOX*COUT)/256, 256>>>(gn1_g, gn1_b);
    k_tconv<COUT,1><<<BB*NTILE, 256, SMEM_B>>>(conv2_b);
    k_se<<<BB, 128>>>(se_w1, se_b1, se_w2, se_b2, gn2_g, gn2_b);
    k_pt<<<BB*(NPTS/32), 256>>>(features, pt_b);
    k_ptab<<<(BB*COUT + 255)/256, 256>>>(ptgn_g, ptgn_b);
    k_out<<<BB*NPTS/64, 256>>>(out);
}

// round 15
// speedup vs baseline: 1.0331x; 1.0331x over previous
#include <cuda_runtime.h>
#include <math.h>
#include <stdint.h>

#define BB 8
#define CIN 64
#define COUT 128
#define NPTS 32768
#define RES 32
#define NVOX (RES*RES*RES)
#define GEPS 1e-5f

#define PX 34
#define PY 34
#define PZ 34
#define PVOX (PX*PY*PZ)          // 39304
#define SLK 2048                 // halo slack rows each side (max reach 1191)
#define NTILE 308                // ceil(PVOX/128)

// conv smem partition (floats): KC=32
#define A_STRIDE 36
#define A_BUF (132*A_STRIDE)              // 4752 per buffer
#define B_SLOT 4096                       // one tap shuffled: 128n x 32k
#define SMEM_FLOATS (2*A_BUF + 4*B_SLOT)  // 25888 floats = 103552 B -> 2 CTAs/SM

// ---------------- scratch (static device globals; no allocation) -------------
__device__ float d_msum[BB*3];
__device__ unsigned d_smaxu[BB];
__device__ float d_normc[BB*3*NPTS];
__device__ __align__(16) float d_gp0[((long)BB*PVOX + 2*SLK)*CIN];   // padded tf32 in (conv1)
__device__ __align__(16) float d_gp1[((long)BB*PVOX + 2*SLK)*COUT];  // conv1 out -> gn1 in-place -> conv2 in
__device__ float d_cnt[BB*NVOX];
__device__ float d_grid2[(long)BB*NVOX*COUT];   // compact conv2 out
__device__ float d_pt[(long)BB*NPTS*COUT];      // point branch
// shuffled weights: [tap][ck][nblk(16)][ks(4)][lane(32)] float2 {k, k+4}
__device__ __align__(16) float2 d_wbs1[27*2*16*4*32];   // conv1: NCK=2
__device__ __align__(16) float2 d_wbs2[27*4*16*4*32];   // conv2: NCK=4
__device__ float d_ptw[CIN*COUT];
__device__ float d_gstats1[BB*8*2];
__device__ float d_cstats2[BB*COUT*2];
__device__ float d_ptstats[BB*8*2];
__device__ float d_A[BB*COUT];
__device__ float d_Bc[BB*COUT];
__device__ float d_ptA[BB*COUT];
__device__ float d_ptB[BB*COUT];

// ---------------- helpers -----------------------------------------------------
__device__ __forceinline__ float rtf32(float x) {
    float r; asm("cvt.rna.tf32.f32 %0, %1;" : "=f"(r) : "f"(x)); return r;
}
__device__ __forceinline__ uint32_t smem_u32(const void* p) {
    uint32_t a;
    asm("{ .reg .u64 t; cvta.to.shared.u64 t, %1; cvt.u32.u64 %0, t; }" : "=r"(a) : "l"(p));
    return a;
}
__device__ __forceinline__ void cpa16(uint32_t dst, const void* src) {
    asm volatile("cp.async.cg.shared.global [%0], [%1], 16;" :: "r"(dst), "l"(src));
}
__device__ __forceinline__ void mma_tf32(float& d0, float& d1, float& d2, float& d3,
                                         uint32_t a0, uint32_t a1, uint32_t a2, uint32_t a3,
                                         uint32_t b0, uint32_t b1) {
    asm volatile(
        "mma.sync.aligned.m16n8k8.row.col.f32.tf32.tf32.f32 "
        "{%0,%1,%2,%3}, {%4,%5,%6,%7}, {%8,%9}, {%0,%1,%2,%3};"
        : "+f"(d0), "+f"(d1), "+f"(d2), "+f"(d3)
        : "r"(a0), "r"(a1), "r"(a2), "r"(a3), "r"(b0), "r"(b1));
}

// ---------------- prep: weights -> shuffled fragment layout -------------------
// d_wbs[((tap*NCK + ck)*16 + nblk)*4 + ks][lane] = {w[n][klo], w[n][khi]}
// n = nblk*8 + (lane>>2); klo = ck*32 + ks*8 + (lane&3); khi = klo + 4.
__global__ void k_prep(const float* __restrict__ w1, const float* __restrict__ w2,
                       const float* __restrict__ ptw) {
    int i = blockIdx.x * 256 + threadIdx.x;          // covers 27*4*2048
    int lane = i & 31, ks = (i >> 5) & 3, nblk = (i >> 7) & 15;
    int q = lane >> 2, rr = lane & 3;
    int n = nblk*8 + q;
    if (i < 27*2*2048) {                             // conv1, NCK=2
        int ck = (i >> 11) & 1; int tap = i >> 12;
        int klo = ck*32 + ks*8 + rr;
        d_wbs1[i] = make_float2(rtf32(w1[(n*CIN + klo)*27 + tap]),
                                rtf32(w1[(n*CIN + klo + 4)*27 + tap]));
    }
    if (i < 27*4*2048) {                             // conv2, NCK=4
        int ck = (i >> 11) & 3; int tap = i >> 13;
        int klo = ck*32 + ks*8 + rr;
        d_wbs2[i] = make_float2(rtf32(w2[(n*COUT + klo)*27 + tap]),
                                rtf32(w2[(n*COUT + klo + 4)*27 + tap]));
    }
    if (i < CIN*COUT) {
        int o = i & 127; int ci = i >> 7;
        d_ptw[i] = ptw[o*CIN + ci];
    }
}

// zero only gp0 INTERIOR (pads are statically zero and never written) + small bufs
__global__ void k_zero0() {
    long i = (long)blockIdx.x * 256 + threadIdx.x;   // BB*NVOX*CIN threads
    int c = i & 63; int v = (int)((i >> 6) & (NVOX-1)); int b = (int)(i >> 21);
    int x = v >> 10, y = (v >> 5) & 31, z = v & 31;
    int pp = ((x+1)*PY + (y+1))*PZ + (z+1);
    d_gp0[((long)SLK + (long)b*PVOX + pp)*CIN + c] = 0.f;
    if (i < BB*NVOX)   d_cnt[i] = 0.f;
    if (i < BB*8*2)    d_gstats1[i] = 0.f;
    if (i < BB*COUT*2) d_cstats2[i] = 0.f;
    if (i < BB*8*2)    d_ptstats[i] = 0.f;
    if (i < BB*3)      d_msum[i] = 0.f;
    if (i < BB)        d_smaxu[i] = 0u;
}

// ---------------- voxelize coords ---------------------------------------------
__global__ void k_mean1(const float* __restrict__ coords) {
    int blk = blockIdx.x;
    int chunk = blk & 15; int d = (blk >> 4) % 3; int b = blk / 48;
    __shared__ float s[256];
    float acc = 0.f;
    int base = (b*3 + d)*NPTS + chunk*2048;
    for (int n = threadIdx.x; n < 2048; n += 256) acc += coords[base + n];
    s[threadIdx.x] = acc; __syncthreads();
    for (int o = 128; o > 0; o >>= 1) {
        if (threadIdx.x < o) s[threadIdx.x] += s[threadIdx.x + o];
        __syncthreads();
    }
    if (threadIdx.x == 0) atomicAdd(&d_msum[b*3 + d], s[0]);
}

__global__ void k_scale1(const float* __restrict__ coords) {
    int blk = blockIdx.x;
    int chunk = blk & 15; int b = blk >> 4;
    float mx = d_msum[b*3]   * (1.f/(float)NPTS);
    float my = d_msum[b*3+1] * (1.f/(float)NPTS);
    float mz = d_msum[b*3+2] * (1.f/(float)NPTS);
    __shared__ float s[256];
    float m = 0.f;
    int n0 = chunk*2048;
    for (int n = threadIdx.x; n < 2048; n += 256) {
        float x = coords[(b*3+0)*NPTS + n0 + n] - mx;
        float y = coords[(b*3+1)*NPTS + n0 + n] - my;
        float z = coords[(b*3+2)*NPTS + n0 + n] - mz;
        m = fmaxf(m, sqrtf(x*x + y*y + z*z));
    }
    s[threadIdx.x] = m; __syncthreads();
    for (int o = 128; o > 0; o >>= 1) {
        if (threadIdx.x < o) s[threadIdx.x] = fmaxf(s[threadIdx.x], s[threadIdx.x + o]);
        __syncthreads();
    }
    if (threadIdx.x == 0) atomicMax(&d_smaxu[b], __float_as_uint(s[0]));
}

__global__ void k_norm(const float* __restrict__ coords) {
    int i = blockIdx.x * 256 + threadIdx.x;
    if (i >= BB*3*NPTS) return;
    int b = i / (3*NPTS); int d = (i / NPTS) % 3;
    float mean = d_msum[b*3 + d] * (1.f/(float)NPTS);
    float scale = __uint_as_float(d_smaxu[b]) * 2.f;
    float t = (coords[i] - mean) / scale + 0.5f;
    d_normc[i] = fminf(fmaxf(t * (float)RES, 0.f), (float)(RES - 1));
}

// ---------------- scatter-mean voxelization into padded grid -----------------
__global__ void k_scatter(const float* __restrict__ feat) {
    int warp = threadIdx.x >> 5, lane = threadIdx.x & 31;
    int p = blockIdx.x * 8 + warp;
    int b = p >> 15, n = p & (NPTS - 1);
    int ix = min(max((int)rintf(d_normc[(b*3+0)*NPTS + n]), 0), RES-1);
    int iy = min(max((int)rintf(d_normc[(b*3+1)*NPTS + n]), 0), RES-1);
    int iz = min(max((int)rintf(d_normc[(b*3+2)*NPTS + n]), 0), RES-1);
    int pp = ((ix+1)*PY + (iy+1))*PZ + (iz+1);
    const float* frow = feat + (long)b*CIN*NPTS + n;
    float v0 = frow[(long)lane * NPTS];
    float v1 = frow[(long)(lane + 32) * NPTS];
    float* row = d_gp0 + ((long)SLK + (long)b*PVOX + pp) * CIN;
    atomicAdd(&row[lane],      v0);
    atomicAdd(&row[lane + 32], v1);
    if (lane == 0) atomicAdd(&d_cnt[b*NVOX + ((ix*RES + iy)*RES + iz)], 1.f);
}

__global__ void k_div() {
    long i = (long)blockIdx.x * 256 + threadIdx.x;
    int c = i & 63; int v = (int)((i >> 6) & (NVOX-1)); int b = (int)(i >> 21);
    int x = v >> 10, y = (v >> 5) & 31, z = v & 31;
    int pp = ((x+1)*PY + (y+1))*PZ + (z+1);
    float cntv = fmaxf(d_cnt[b*NVOX + v], 1.f);
    float* a = d_gp0 + ((long)SLK + (long)b*PVOX + pp) * CIN + c;
    *a = rtf32(*a / cntv);
}

// ---------------- tf32 mma.sync implicit-GEMM 3x3x3 conv ----------------------
// M=128, 256 thr = 8 warps (4m x 2n), 2 CTAs/SM (103.5 KB smem).
// Stage-top holds A(s)+B_t0(s); issue [B_t1][B_t2][A(s+1)+B_t0(s+1)];
// single wait(1) after dz0 drains BOTH B_t1 and B_t2 (oldest-first), so
// dz1+dz2 run back-to-back: 2 waits + 2 syncs per stage total.
// STAGE 0: padded gp1 + fused GN1 group stats; STAGE 1: grid2 + channel stats.
template<int CI, int STAGE>
__global__ void __launch_bounds__(256, 2) k_tconv(const float* __restrict__ bias) {
    extern __shared__ float sm[];
    const int NCK = CI / 32;
    const int NS = 9 * NCK;

    const float*  __restrict__ gin = (STAGE == 0) ? (d_gp0 + (long)SLK*CI)
                                                  : (d_gp1 + (long)SLK*CI);
    const float2* __restrict__ wbs = (STAGE == 0) ? d_wbs1 : d_wbs2;

    int blk = blockIdx.x;                   // BB*NTILE
    int b = blk / NTILE, tile = blk % NTILE;
    long pbase = (long)b * PVOX + tile * 128;

    int tid = threadIdx.x, warp = tid >> 5, lane = tid & 31;
    int wm = warp & 3, wn = warp >> 2;
    uint32_t smb = smem_u32(sm);
    uint32_t aAu[2] = { smb, smb + A_BUF*4 };
    uint32_t aBbase = smb + 2*A_BUF*4;

    float acc[2][8][4];
    #pragma unroll
    for (int mi = 0; mi < 2; mi++)
        #pragma unroll
        for (int ni = 0; ni < 8; ni++)
            #pragma unroll
            for (int j = 0; j < 4; j++) acc[mi][ni][j] = 0.f;

    int q = lane >> 2, rr = lane & 3;
    int aoffs = (wm*32 + q)*A_STRIDE + rr;
    int boffs2 = (wn*8)*128 + lane;

    auto issue_A = [&](int s, int abuf) {
        int dxy = s / NCK, ck = s - (s / NCK) * NCK;
        int dxx = dxy / 3 - 1, dyy = dxy % 3 - 1;
        long astart = pbase + dxx * (PY*PZ) + dyy * PZ - 1;
        const float* asrc = gin + astart * CI + ck * 32;
        uint32_t aA = aAu[abuf];
        #pragma unroll
        for (int o2 = 0; o2 < 5; o2++) {
            int i = o2 * 256 + tid;
            if (i < 130*8) {
                int r = i >> 3, seg = i & 7;
                cpa16(aA + (uint32_t)(r*(A_STRIDE*4) + seg*16), asrc + (long)r * CI + seg*4);
            }
        }
    };
    auto issue_B = [&](int s, int dz, int slot) {
        int dxy = s / NCK, ck = s - (s / NCK) * NCK;
        int tap = dxy*3 + dz;
        const float2* bsrc = wbs + (long)(tap * NCK + ck) * 2048;
        uint32_t aB = aBbase + (uint32_t)slot * (B_SLOT*4);
        #pragma unroll
        for (int o2 = 0; o2 < 4; o2++) {
            int i = o2 * 256 + tid;
            cpa16(aB + (uint32_t)(i*16), (const char*)bsrc + i*16);
        }
    };
    auto compute = [&](int abuf, int slot, int dz) {
        const uint32_t* sAu = (const uint32_t*)sm + abuf*A_BUF;
        const float2* sB2 = (const float2*)(sm + 2*A_BUF) + slot*(B_SLOT/2);
        int abase0 = aoffs + dz*A_STRIDE;
        #pragma unroll
        for (int ks = 0; ks < 4; ks++) {
            int k0 = ks * 8;
            uint32_t b0[8], b1[8];
            #pragma unroll
            for (int ni = 0; ni < 8; ni++) {
                float2 bv = sB2[boffs2 + ni*128 + ks*32];
                b0[ni] = __float_as_uint(bv.x);
                b1[ni] = __float_as_uint(bv.y);
            }
            #pragma unroll
            for (int mi = 0; mi < 2; mi++) {
                int abase = abase0 + mi*16*A_STRIDE + k0;
                uint32_t a0 = sAu[abase];
                uint32_t a1 = sAu[abase + 8*A_STRIDE];
                uint32_t a2 = sAu[abase + 4];
                uint32_t a3 = sAu[abase + 8*A_STRIDE + 4];
                #pragma unroll
                for (int ni = 0; ni < 8; ni++)
                    mma_tf32(acc[mi][ni][0], acc[mi][ni][1], acc[mi][ni][2], acc[mi][ni][3],
                             a0, a1, a2, a3, b0[ni], b1[ni]);
            }
        }
    };

    issue_A(0, 0);
    issue_B(0, 0, 0);
    asm volatile("cp.async.commit_group;");

    #pragma unroll 1
    for (int s = 0; s < NS; s++) {
        int abuf = s & 1;
        int sl0 = (3*s) & 3, sl1 = (3*s + 1) & 3, sl2 = (3*s + 2) & 3, sl3 = (3*s + 3) & 3;
        asm volatile("cp.async.wait_group %0;" :: "n"(0) : "memory");
        __syncthreads();
        bool more = (s + 1 < NS);
        issue_B(s, 1, sl1); asm volatile("cp.async.commit_group;");
        issue_B(s, 2, sl2); asm volatile("cp.async.commit_group;");
        if (more) {
            issue_A(s + 1, abuf ^ 1);
            issue_B(s + 1, 0, sl3);
            asm volatile("cp.async.commit_group;");
        }
        compute(abuf, sl0, 0);
        // drain B_t1 AND B_t2 (the two oldest groups); prefetch stays in flight
        if (more) { asm volatile("cp.async.wait_group %0;" :: "n"(1) : "memory"); }
        else      { asm volatile("cp.async.wait_group %0;" :: "n"(0) : "memory"); }
        __syncthreads();
        compute(abuf, sl1, 1);
        compute(abuf, sl2, 2);
    }
    __syncthreads();

    // ---- epilogue: discard pad rows, add bias, store, fused stats ----
    if (STAGE == 0) { if (tid < 16) sm[tid] = 0.f; }
    else            { if (tid < 256) sm[tid] = 0.f; }
    __syncthreads();

    int cb = wn*64 + rr*2;
    int prow = tile*128 + wm*32 + q;

    float sg[4] = {0.f, 0.f, 0.f, 0.f}, qg[4] = {0.f, 0.f, 0.f, 0.f};

    #pragma unroll
    for (int mi = 0; mi < 2; mi++) {
        #pragma unroll
        for (int half = 0; half < 2; half++) {
            int pp = prow + mi*16 + half*8;
            int zp = pp % PZ; int rem = pp / PZ; int yp = rem % PY; int xp = rem / PY;
            bool valid = (pp < PVOX) && (xp >= 1 && xp <= 32) && (yp >= 1 && yp <= 32)
                         && (zp >= 1 && zp <= 32);
            if (!valid) continue;
            long ob;
            if (STAGE == 0)
                ob = ((long)SLK + (long)b*PVOX + pp) * COUT;
            else
                ob = ((long)b*NVOX + (((xp-1)*RES + (yp-1))*RES + (zp-1))) * COUT;
            float* gout = (STAGE == 0) ? d_gp1 : d_grid2;
            if (STAGE == 0) {
                #pragma unroll
                for (int ni = 0; ni < 8; ni++) {
                    int col = cb + ni*8;
                    float2 o2;
                    o2.x = acc[mi][ni][half*2]   + bias[col];
                    o2.y = acc[mi][ni][half*2+1] + bias[col+1];
                    *(float2*)&gout[ob + col] = o2;
                    int gl = ni >> 1;
                    sg[gl] += o2.x + o2.y;
                    qg[gl] += o2.x*o2.x + o2.y*o2.y;
                }
            } else {
                #pragma unroll
                for (int ni = 0; ni < 8; ni++) {
                    int col = cb + ni*8;
                    float2 o2;
                    o2.x = acc[mi][ni][half*2]   + bias[col];
                    o2.y = acc[mi][ni][half*2+1] + bias[col+1];
                    *(float2*)&gout[ob + col] = o2;
                    acc[mi][ni][half*2]   = o2.x;
                    acc[mi][ni][half*2+1] = o2.y;
                }
            }
        }
    }

    if (STAGE == 0) {
        #pragma unroll
        for (int g = 0; g < 4; g++) {
            #pragma unroll
            for (int off = 16; off > 0; off >>= 1) {
                sg[g] += __shfl_down_sync(0xffffffffu, sg[g], off);
                qg[g] += __shfl_down_sync(0xffffffffu, qg[g], off);
            }
        }
        if (lane == 0) {
            #pragma unroll
            for (int g = 0; g < 4; g++) {
                atomicAdd(&sm[(wn*4 + g)*2 + 0], sg[g]);
                atomicAdd(&sm[(wn*4 + g)*2 + 1], qg[g]);
            }
        }
        __syncthreads();
        if (tid < 16) atomicAdd(&d_gstats1[b*16 + tid], sm[tid]);
    } else {
        #pragma unroll
        for (int ni = 0; ni < 8; ni++) {
            float sx = 0.f, qx = 0.f, sy = 0.f, qy = 0.f;
            #pragma unroll
            for (int mi = 0; mi < 2; mi++) {
                #pragma unroll
                for (int half = 0; half < 2; half++) {
                    int pp = prow + mi*16 + half*8;
                    int zp = pp % PZ; int rem = pp / PZ; int yp = rem % PY; int xp = rem / PY;
                    bool valid = (pp < PVOX) && (xp >= 1 && xp <= 32) && (yp >= 1 && yp <= 32)
                                 && (zp >= 1 && zp <= 32);
                    if (!valid) continue;
                    float vx = acc[mi][ni][half*2], vy = acc[mi][ni][half*2+1];
                    sx += vx; qx += vx*vx; sy += vy; qy += vy*vy;
                }
            }
            #pragma unroll
            for (int off = 4; off <= 16; off <<= 1) {
                sx += __shfl_xor_sync(0xffffffffu, sx, off);
                qx += __shfl_xor_sync(0xffffffffu, qx, off);
                sy += __shfl_xor_sync(0xffffffffu, sy, off);
                qy += __shfl_xor_sync(0xffffffffu, qy, off);
            }
            if (q == 0) {
                int col = cb + ni*8;
                atomicAdd(&sm[col*2 + 0],       sx);
                atomicAdd(&sm[col*2 + 1],       qx);
                atomicAdd(&sm[(col+1)*2 + 0],   sy);
                atomicAdd(&sm[(col+1)*2 + 1],   qy);
            }
        }
        __syncthreads();
        if (tid < 256) atomicAdd(&d_cstats2[b*256 + tid], sm[tid]);
    }
}

// GN1 normalize + swish + rtf32, IN PLACE on gp1 interior
__global__ void k_gn1(const float* __restrict__ g, const float* __restrict__ bt) {
    long i = (long)blockIdx.x * 256 + threadIdx.x;   // BB*NVOX*COUT
    int c = i & 127; int b = (int)(i >> 22);
    int v = (int)((i >> 7) & (NVOX-1));
    int gr = c >> 4;
    float S = d_gstats1[(b*8 + gr)*2], Q = d_gstats1[(b*8 + gr)*2 + 1];
    const float cnt = (float)NVOX * 16.f;
    float mu = S / cnt; float var = Q / cnt - mu*mu;
    float rs = rsqrtf(var + GEPS);
    int x = v >> 10, yy = (v >> 5) & 31, z = v & 31;
    int pp = ((x+1)*PY + (yy+1))*PZ + (z+1);
    long idx = ((long)SLK + (long)b*PVOX + pp)*COUT + c;
    float y = (d_gp1[idx] - mu) * rs * g[c] + bt[c];
    float sw = y / (1.f + expf(-y));
    d_gp1[idx] = rtf32(sw);
}

// ---------------- SE + fold GN2*SE into per-(b,c) affine ---------------------
__global__ void k_se(const float* __restrict__ w1, const float* __restrict__ b1,
                     const float* __restrict__ w2, const float* __restrict__ b2,
                     const float* __restrict__ gamma, const float* __restrict__ beta) {
    int b = blockIdx.x; int c = threadIdx.x;
    __shared__ float s[128], gmu[8], grs[8], s1[16];
    const float cnt = (float)NVOX;
    if (c < 8) {
        float S = 0.f, Q = 0.f;
        for (int j = 0; j < 16; j++) {
            S += d_cstats2[(b*COUT + c*16 + j)*2 + 0];
            Q += d_cstats2[(b*COUT + c*16 + j)*2 + 1];
        }
        float gc = cnt * 16.f;
        float mu = S / gc; float var = Q / gc - mu*mu;
        gmu[c] = mu; grs[c] = rsqrtf(var + GEPS);
    }
    __syncthreads();
    int gr = c >> 4;
    float mu = gmu[gr], rs = grs[gr];
    float csum = d_cstats2[(b*COUT + c)*2];
    s[c] = (csum / cnt - mu) * rs * gamma[c] + beta[c];
    __syncthreads();
    if (c < 16) {
        float a = b1[c];
        for (int j = 0; j < 128; j++) a += w1[c*128 + j] * s[j];
        s1[c] = fmaxf(a, 0.f);
    }
    __syncthreads();
    float a2 = b2[c];
    for (int j = 0; j < 16; j++) a2 += w2[c*16 + j] * s1[j];
    float se = 1.f / (1.f + expf(-a2));
    float rg = rs * gamma[c];
    d_A [b*COUT + c] = rg * se;
    d_Bc[b*COUT + c] = (beta[c] - mu * rg) * se;
}

// ---------------- point branch 1x1 conv + stats --------------------------------
__global__ void k_pt(const float* __restrict__ feat, const float* __restrict__ ptb) {
    int blk = blockIdx.x;
    int b = blk >> 10, n0 = (blk & 1023) * 32;
    __shared__ float fs[CIN*32];
    __shared__ float so[32*COUT];
    __shared__ float ss[256], sq[256];
    for (int e = threadIdx.x; e < CIN*32; e += 256) {
        int ci = e >> 5, nn = e & 31;
        fs[e] = feat[((long)(b*CIN) + ci)*NPTS + n0 + nn];
    }
    __syncthreads();
    int o = threadIdx.x & 127, h = threadIdx.x >> 7;
    float acc[16];
    float bv = ptb[o];
    #pragma unroll
    for (int j = 0; j < 16; j++) acc[j] = bv;
    for (int ci = 0; ci < CIN; ci++) {
        float w = d_ptw[ci*COUT + o];
        #pragma unroll
        for (int j = 0; j < 16; j++)
            acc[j] = fmaf(w, fs[ci*32 + h*16 + j], acc[j]);
    }
    float s = 0.f, q = 0.f;
    #pragma unroll
    for (int j = 0; j < 16; j++) {
        s += acc[j]; q += acc[j]*acc[j];
        so[(h*16 + j)*COUT + o] = acc[j];
    }
    ss[threadIdx.x] = s; sq[threadIdx.x] = q;
    __syncthreads();
    if (threadIdx.x < 8) {
        float S = 0.f, Q = 0.f;
        for (int j = 0; j < 16; j++) {
            int cc = threadIdx.x*16 + j;
            S += ss[cc] + ss[cc+128]; Q += sq[cc] + sq[cc+128];
        }
        atomicAdd(&d_ptstats[(b*8 + threadIdx.x)*2 + 0], S);
        atomicAdd(&d_ptstats[(b*8 + threadIdx.x)*2 + 1], Q);
    }
    for (int e = threadIdx.x; e < 32*COUT; e += 256) {
        int nn = e >> 7, oo = e & 127;
        d_pt[((long)(b*NPTS) + n0 + nn)*COUT + oo] = so[e];
    }
}

__global__ void k_ptab(const float* __restrict__ g, const float* __restrict__ bt) {
    int i = blockIdx.x * 256 + threadIdx.x;
    if (i >= BB*COUT) return;
    int b = i >> 7, c = i & 127, gr = c >> 4;
    const float cnt = 16.f * (float)NPTS;
    float S = d_ptstats[(b*8 + gr)*2], Q = d_ptstats[(b*8 + gr)*2 + 1];
    float mu = S / cnt, var = Q / cnt - mu*mu, rs = rsqrtf(var + GEPS);
    d_ptA[i] = rs * g[c];
    d_ptB[i] = bt[c] - mu * rs * g[c];
}

// ---------------- trilinear devoxelize + point add -> out (coalesced) ---------
__global__ void k_out(float* __restrict__ out) {
    __shared__ float so[64*132];
    int warp = threadIdx.x >> 5, lane = threadIdx.x & 31;
    int blk = blockIdx.x;
    int b = blk >> 9;
    int n0 = (blk & 511) * 64;

    #pragma unroll 1
    for (int pass = 0; pass < 8; pass++) {
        int pt = pass * 8 + warp;
        int n = n0 + pt;
        float nx = d_normc[(b*3+0)*NPTS + n];
        float ny = d_normc[(b*3+1)*NPTS + n];
        float nz = d_normc[(b*3+2)*NPTS + n];
        int lx = (int)floorf(nx); float fx = nx - (float)lx; int hx = min(lx+1, RES-1);
        int ly = (int)floorf(ny); float fy = ny - (float)ly; int hy = min(ly+1, RES-1);
        int lz = (int)floorf(nz); float fz = nz - (float)lz; int hz = min(lz+1, RES-1);

        float4 acc = make_float4(0.f, 0.f, 0.f, 0.f);
        float sumw = 0.f;
        const float4* gp = (const float4*)d_grid2;
        #pragma unroll
        for (int k = 0; k < 8; k++) {
            int dx = k >> 2, dy = (k >> 1) & 1, dz = k & 1;
            int ix = dx ? hx : lx, iy = dy ? hy : ly, iz = dz ? hz : lz;
            float w = (dx ? fx : 1.f - fx) * (dy ? fy : 1.f - fy) * (dz ? fz : 1.f - fz);
            long row = ((long)(b*NVOX) + (ix*RES + iy)*RES + iz) * (COUT/4);
            float4 v = gp[row + lane];
            acc.x += w*v.x; acc.y += w*v.y; acc.z += w*v.z; acc.w += w*v.w;
            sumw += w;
        }
        float4 a  = ((const float4*)d_A )[b*32 + lane];
        float4 bc = ((const float4*)d_Bc)[b*32 + lane];
        float4 gv;
        gv.x = acc.x*a.x + sumw*bc.x; gv.y = acc.y*a.y + sumw*bc.y;
        gv.z = acc.z*a.z + sumw*bc.z; gv.w = acc.w*a.w + sumw*bc.w;

        float4 pv = ((const float4*)d_pt)[((long)(b*NPTS) + n)*32 + lane];
        float4 pa = ((const float4*)d_ptA)[b*32 + lane];
        float4 pb = ((const float4*)d_ptB)[b*32 + lane];
        float y;
        y = pv.x*pa.x + pb.x; gv.x += y / (1.f + expf(-y));
        y = pv.y*pa.y + pb.y; gv.y += y / (1.f + expf(-y));
        y = pv.z*pa.z + pb.z; gv.z += y / (1.f + expf(-y));
        y = pv.w*pa.w + pb.w; gv.w += y / (1.f + expf(-y));

        ((float4*)(so + pt*132))[lane] = gv;
    }
    __syncthreads();
    for (int e = threadIdx.x; e < 64*128; e += 256) {
        int c = e >> 6, n = e & 63;
        out[((long)(b*COUT) + c)*NPTS + n0 + n] = so[n*132 + c];
    }
}

// ---------------- launch --------------------------------------------------------
extern "C" void kernel_launch(void* const* d_in, const int* in_sizes, int n_in,
                              void* d_out, int out_size) {
    const float* features = (const float*)d_in[0];
    const float* coords   = (const float*)d_in[1];
    const float* conv1_w  = (const float*)d_in[2];
    const float* conv1_b  = (const float*)d_in[3];
    const float* gn1_g    = (const float*)d_in[4];
    const float* gn1_b    = (const float*)d_in[5];
    const float* conv2_w  = (const float*)d_in[6];
    const float* conv2_b  = (const float*)d_in[7];
    const float* gn2_g    = (const float*)d_in[8];
    const float* gn2_b    = (const float*)d_in[9];
    const float* se_w1    = (const float*)d_in[10];
    const float* se_b1    = (const float*)d_in[11];
    const float* se_w2    = (const float*)d_in[12];
    const float* se_b2    = (const float*)d_in[13];
    const float* pt_w     = (const float*)d_in[14];
    const float* pt_b     = (const float*)d_in[15];
    const float* ptgn_g   = (const float*)d_in[16];
    const float* ptgn_b   = (const float*)d_in[17];
    float* out = (float*)d_out;

    const int SMEM_B = SMEM_FLOATS * 4;    // 103552
    cudaFuncSetAttribute(k_tconv<CIN,0>,  cudaFuncAttributeMaxDynamicSharedMemorySize, SMEM_B);
    cudaFuncSetAttribute(k_tconv<COUT,1>, cudaFuncAttributeMaxDynamicSharedMemorySize, SMEM_B);

    k_prep<<<(27*4*2048 + 255)/256, 256>>>(conv1_w, conv2_w, pt_w);
    k_zero0<<<(int)(((long)BB*NVOX*CIN)/256), 256>>>();
    k_mean1<<<BB*3*16, 256>>>(coords);
    k_scale1<<<BB*16, 256>>>(coords);
    k_norm<<<(BB*3*NPTS + 255)/256, 256>>>(coords);
    k_scatter<<<BB*NPTS/8, 256>>>(features);
    k_div<<<(BB*NVOX*CIN)/256, 256>>>();
    k_tconv<CIN,0><<<BB*NTILE, 256, SMEM_B>>>(conv1_b);
    k_gn1<<<(BB*NVOX*COUT)/256, 256>>>(gn1_g, gn1_b);
    k_tconv<COUT,1><<<BB*NTILE, 256, SMEM_B>>>(conv2_b);
    k_se<<<BB, 128>>>(se_w1, se_b1, se_w2, se_b2, gn2_g, gn2_b);
    k_pt<<<BB*(NPTS/32), 256>>>(features, pt_b);
    k_ptab<<<(BB*COUT + 255)/256, 256>>>(ptgn_g, ptgn_b);
    k_out<<<BB*NPTS/64, 256>>>(out);
}

// round 16
// speedup vs baseline: 1.0502x; 1.0166x over previous
#include <cuda_runtime.h>
#include <math.h>
#include <stdint.h>

#define BB 8
#define CIN 64
#define COUT 128
#define NPTS 32768
#define RES 32
#define NVOX (RES*RES*RES)
#define GEPS 1e-5f

#define PX 34
#define PY 34
#define PZ 34
#define PVOX (PX*PY*PZ)          // 39304
#define SLK 2048                 // halo slack rows each side (max reach 1191)
#define NTILE 308                // ceil(PVOX/128)

// conv smem partition (floats): KC=32
#define A_STRIDE 36
#define A_BUF (132*A_STRIDE)              // 4752 per buffer
#define B_SLOT 4096                       // one tap shuffled: 128n x 32k
#define SMEM_FLOATS (2*A_BUF + 4*B_SLOT)  // 25888 floats = 103552 B -> 2 CTAs/SM

// ---------------- scratch (static device globals; no allocation) -------------
__device__ float d_msum[BB*3];
__device__ unsigned d_smaxu[BB];
__device__ float d_normc[BB*3*NPTS];
__device__ __align__(16) float d_gp0[((long)BB*PVOX + 2*SLK)*CIN];   // padded tf32 in (conv1)
__device__ __align__(16) float d_gp1[((long)BB*PVOX + 2*SLK)*COUT];  // conv1 out -> gn1 in-place -> conv2 in
__device__ float d_cnt[BB*NVOX];
__device__ float d_grid2[(long)BB*NVOX*COUT];   // compact conv2 out
__device__ float d_pt[(long)BB*NPTS*COUT];      // point branch
// shuffled weights: [tap][ck][nblk(16)][ks(4)][lane(32)] float2 {k, k+4}
__device__ __align__(16) float2 d_wbs1[27*2*16*4*32];   // conv1: NCK=2
__device__ __align__(16) float2 d_wbs2[27*4*16*4*32];   // conv2: NCK=4
__device__ float d_ptw[CIN*COUT];
__device__ float d_gstats1[BB*8*2];
__device__ float d_cstats2[BB*COUT*2];
__device__ float d_ptstats[BB*8*2];
__device__ float d_A[BB*COUT];
__device__ float d_Bc[BB*COUT];
__device__ float d_ptA[BB*COUT];
__device__ float d_ptB[BB*COUT];

// ---------------- helpers -----------------------------------------------------
__device__ __forceinline__ float rtf32(float x) {
    float r; asm("cvt.rna.tf32.f32 %0, %1;" : "=f"(r) : "f"(x)); return r;
}
__device__ __forceinline__ uint32_t smem_u32(const void* p) {
    uint32_t a;
    asm("{ .reg .u64 t; cvta.to.shared.u64 t, %1; cvt.u32.u64 %0, t; }" : "=r"(a) : "l"(p));
    return a;
}
__device__ __forceinline__ void cpa16(uint32_t dst, const void* src) {
    asm volatile("cp.async.cg.shared.global [%0], [%1], 16;" :: "r"(dst), "l"(src));
}
__device__ __forceinline__ void mma_tf32(float& d0, float& d1, float& d2, float& d3,
                                         uint32_t a0, uint32_t a1, uint32_t a2, uint32_t a3,
                                         uint32_t b0, uint32_t b1) {
    asm volatile(
        "mma.sync.aligned.m16n8k8.row.col.f32.tf32.tf32.f32 "
        "{%0,%1,%2,%3}, {%4,%5,%6,%7}, {%8,%9}, {%0,%1,%2,%3};"
        : "+f"(d0), "+f"(d1), "+f"(d2), "+f"(d3)
        : "r"(a0), "r"(a1), "r"(a2), "r"(a3), "r"(b0), "r"(b1));
}

// ---------------- prep: weights -> shuffled fragment layout -------------------
__global__ void k_prep(const float* __restrict__ w1, const float* __restrict__ w2,
                       const float* __restrict__ ptw) {
    int i = blockIdx.x * 256 + threadIdx.x;          // covers 27*4*2048
    int lane = i & 31, ks = (i >> 5) & 3, nblk = (i >> 7) & 15;
    int q = lane >> 2, rr = lane & 3;
    int n = nblk*8 + q;
    if (i < 27*2*2048) {                             // conv1, NCK=2
        int ck = (i >> 11) & 1; int tap = i >> 12;
        int klo = ck*32 + ks*8 + rr;
        d_wbs1[i] = make_float2(rtf32(w1[(n*CIN + klo)*27 + tap]),
                                rtf32(w1[(n*CIN + klo + 4)*27 + tap]));
    }
    if (i < 27*4*2048) {                             // conv2, NCK=4
        int ck = (i >> 11) & 3; int tap = i >> 13;
        int klo = ck*32 + ks*8 + rr;
        d_wbs2[i] = make_float2(rtf32(w2[(n*COUT + klo)*27 + tap]),
                                rtf32(w2[(n*COUT + klo + 4)*27 + tap]));
    }
    if (i < CIN*COUT) {
        int o = i & 127; int ci = i >> 7;
        d_ptw[i] = ptw[o*CIN + ci];
    }
}

// zero only gp0 INTERIOR (pads are statically zero and never written) + small bufs
__global__ void k_zero0() {
    long i = (long)blockIdx.x * 256 + threadIdx.x;   // BB*NVOX*CIN threads
    int c = i & 63; int v = (int)((i >> 6) & (NVOX-1)); int b = (int)(i >> 21);
    int x = v >> 10, y = (v >> 5) & 31, z = v & 31;
    int pp = ((x+1)*PY + (y+1))*PZ + (z+1);
    d_gp0[((long)SLK + (long)b*PVOX + pp)*CIN + c] = 0.f;
    if (i < BB*NVOX)   d_cnt[i] = 0.f;
    if (i < BB*8*2)    d_gstats1[i] = 0.f;
    if (i < BB*COUT*2) d_cstats2[i] = 0.f;
    if (i < BB*8*2)    d_ptstats[i] = 0.f;
    if (i < BB*3)      d_msum[i] = 0.f;
    if (i < BB)        d_smaxu[i] = 0u;
}

// ---------------- voxelize coords ---------------------------------------------
__global__ void k_mean1(const float* __restrict__ coords) {
    int blk = blockIdx.x;
    int chunk = blk & 15; int d = (blk >> 4) % 3; int b = blk / 48;
    __shared__ float s[256];
    float acc = 0.f;
    int base = (b*3 + d)*NPTS + chunk*2048;
    for (int n = threadIdx.x; n < 2048; n += 256) acc += coords[base + n];
    s[threadIdx.x] = acc; __syncthreads();
    for (int o = 128; o > 0; o >>= 1) {
        if (threadIdx.x < o) s[threadIdx.x] += s[threadIdx.x + o];
        __syncthreads();
    }
    if (threadIdx.x == 0) atomicAdd(&d_msum[b*3 + d], s[0]);
}

__global__ void k_scale1(const float* __restrict__ coords) {
    int blk = blockIdx.x;
    int chunk = blk & 15; int b = blk >> 4;
    float mx = d_msum[b*3]   * (1.f/(float)NPTS);
    float my = d_msum[b*3+1] * (1.f/(float)NPTS);
    float mz = d_msum[b*3+2] * (1.f/(float)NPTS);
    __shared__ float s[256];
    float m = 0.f;
    int n0 = chunk*2048;
    for (int n = threadIdx.x; n < 2048; n += 256) {
        float x = coords[(b*3+0)*NPTS + n0 + n] - mx;
        float y = coords[(b*3+1)*NPTS + n0 + n] - my;
        float z = coords[(b*3+2)*NPTS + n0 + n] - mz;
        m = fmaxf(m, sqrtf(x*x + y*y + z*z));
    }
    s[threadIdx.x] = m; __syncthreads();
    for (int o = 128; o > 0; o >>= 1) {
        if (threadIdx.x < o) s[threadIdx.x] = fmaxf(s[threadIdx.x], s[threadIdx.x + o]);
        __syncthreads();
    }
    if (threadIdx.x == 0) atomicMax(&d_smaxu[b], __float_as_uint(s[0]));
}

__global__ void k_norm(const float* __restrict__ coords) {
    int i = blockIdx.x * 256 + threadIdx.x;
    if (i >= BB*3*NPTS) return;
    int b = i / (3*NPTS); int d = (i / NPTS) % 3;
    float mean = d_msum[b*3 + d] * (1.f/(float)NPTS);
    float scale = __uint_as_float(d_smaxu[b]) * 2.f;
    float t = (coords[i] - mean) / scale + 0.5f;
    d_normc[i] = fminf(fmaxf(t * (float)RES, 0.f), (float)(RES - 1));
}

// ---------------- scatter-mean voxelization into padded grid -----------------
// 256 thr / 32 points: stage 64ch x 32pt tile through smem (coalesced reads),
// then each warp scatters 4 points (atomics coalesced as before).
__global__ void k_scatter(const float* __restrict__ feat) {
    __shared__ float fs[CIN*32];           // [c][nn]
    int blk = blockIdx.x;                  // BB*NPTS/32
    int b = blk >> 10, n0 = (blk & 1023) * 32;
    int tid = threadIdx.x, warp = tid >> 5, lane = tid & 31;

    const float* fb = feat + (long)b*CIN*NPTS + n0;
    #pragma unroll
    for (int o2 = 0; o2 < 8; o2++) {
        int e = o2 * 256 + tid;            // e = c*32 + nn
        int c = e >> 5, nn = e & 31;
        fs[e] = fb[(long)c * NPTS + nn];
    }
    __syncthreads();

    #pragma unroll
    for (int j = 0; j < 4; j++) {
        int pt = warp * 4 + j;
        int n = n0 + pt;
        int ix = min(max((int)rintf(d_normc[(b*3+0)*NPTS + n]), 0), RES-1);
        int iy = min(max((int)rintf(d_normc[(b*3+1)*NPTS + n]), 0), RES-1);
        int iz = min(max((int)rintf(d_normc[(b*3+2)*NPTS + n]), 0), RES-1);
        int pp = ((ix+1)*PY + (iy+1))*PZ + (iz+1);
        float* row = d_gp0 + ((long)SLK + (long)b*PVOX + pp) * CIN;
        atomicAdd(&row[lane],      fs[lane*32 + pt]);
        atomicAdd(&row[lane + 32], fs[(lane+32)*32 + pt]);
        if (lane == 0) atomicAdd(&d_cnt[b*NVOX + ((ix*RES + iy)*RES + iz)], 1.f);
    }
}

__global__ void k_div() {
    long i = (long)blockIdx.x * 256 + threadIdx.x;
    int c = i & 63; int v = (int)((i >> 6) & (NVOX-1)); int b = (int)(i >> 21);
    int x = v >> 10, y = (v >> 5) & 31, z = v & 31;
    int pp = ((x+1)*PY + (y+1))*PZ + (z+1);
    float cntv = fmaxf(d_cnt[b*NVOX + v], 1.f);
    float* a = d_gp0 + ((long)SLK + (long)b*PVOX + pp) * CIN + c;
    *a = rtf32(*a / cntv);
}

// ---------------- tf32 mma.sync implicit-GEMM 3x3x3 conv ----------------------
// M=128, 256 thr = 8 warps (4m x 2n), 2 CTAs/SM (103.5 KB smem).
// Stage-top holds A(s)+B_t0(s); issue [B_t1][B_t2][A(s+1)+B_t0(s+1)];
// single wait(1) after dz0 drains BOTH B_t1 and B_t2 (oldest-first), so
// dz1+dz2 run back-to-back: 2 waits + 2 syncs per stage total.
// STAGE 0: padded gp1 + fused GN1 group stats; STAGE 1: grid2 + channel stats.
template<int CI, int STAGE>
__global__ void __launch_bounds__(256, 2) k_tconv(const float* __restrict__ bias) {
    extern __shared__ float sm[];
    const int NCK = CI / 32;
    const int NS = 9 * NCK;

    const float*  __restrict__ gin = (STAGE == 0) ? (d_gp0 + (long)SLK*CI)
                                                  : (d_gp1 + (long)SLK*CI);
    const float2* __restrict__ wbs = (STAGE == 0) ? d_wbs1 : d_wbs2;

    int blk = blockIdx.x;                   // BB*NTILE
    int b = blk / NTILE, tile = blk % NTILE;
    long pbase = (long)b * PVOX + tile * 128;

    int tid = threadIdx.x, warp = tid >> 5, lane = tid & 31;
    int wm = warp & 3, wn = warp >> 2;
    uint32_t smb = smem_u32(sm);
    uint32_t aAu[2] = { smb, smb + A_BUF*4 };
    uint32_t aBbase = smb + 2*A_BUF*4;

    float acc[2][8][4];
    #pragma unroll
    for (int mi = 0; mi < 2; mi++)
        #pragma unroll
        for (int ni = 0; ni < 8; ni++)
            #pragma unroll
            for (int j = 0; j < 4; j++) acc[mi][ni][j] = 0.f;

    int q = lane >> 2, rr = lane & 3;
    int aoffs = (wm*32 + q)*A_STRIDE + rr;
    int boffs2 = (wn*8)*128 + lane;

    auto issue_A = [&](int s, int abuf) {
        int dxy = s / NCK, ck = s - (s / NCK) * NCK;
        int dxx = dxy / 3 - 1, dyy = dxy % 3 - 1;
        long astart = pbase + dxx * (PY*PZ) + dyy * PZ - 1;
        const float* asrc = gin + astart * CI + ck * 32;
        uint32_t aA = aAu[abuf];
        #pragma unroll
        for (int o2 = 0; o2 < 5; o2++) {
            int i = o2 * 256 + tid;
            if (i < 130*8) {
                int r = i >> 3, seg = i & 7;
                cpa16(aA + (uint32_t)(r*(A_STRIDE*4) + seg*16), asrc + (long)r * CI + seg*4);
            }
        }
    };
    auto issue_B = [&](int s, int dz, int slot) {
        int dxy = s / NCK, ck = s - (s / NCK) * NCK;
        int tap = dxy*3 + dz;
        const float2* bsrc = wbs + (long)(tap * NCK + ck) * 2048;
        uint32_t aB = aBbase + (uint32_t)slot * (B_SLOT*4);
        #pragma unroll
        for (int o2 = 0; o2 < 4; o2++) {
            int i = o2 * 256 + tid;
            cpa16(aB + (uint32_t)(i*16), (const char*)bsrc + i*16);
        }
    };
    auto compute = [&](int abuf, int slot, int dz) {
        const uint32_t* sAu = (const uint32_t*)sm + abuf*A_BUF;
        const float2* sB2 = (const float2*)(sm + 2*A_BUF) + slot*(B_SLOT/2);
        int abase0 = aoffs + dz*A_STRIDE;
        #pragma unroll
        for (int ks = 0; ks < 4; ks++) {
            int k0 = ks * 8;
            uint32_t b0[8], b1[8];
            #pragma unroll
            for (int ni = 0; ni < 8; ni++) {
                float2 bv = sB2[boffs2 + ni*128 + ks*32];
                b0[ni] = __float_as_uint(bv.x);
                b1[ni] = __float_as_uint(bv.y);
            }
            #pragma unroll
            for (int mi = 0; mi < 2; mi++) {
                int abase = abase0 + mi*16*A_STRIDE + k0;
                uint32_t a0 = sAu[abase];
                uint32_t a1 = sAu[abase + 8*A_STRIDE];
                uint32_t a2 = sAu[abase + 4];
                uint32_t a3 = sAu[abase + 8*A_STRIDE + 4];
                #pragma unroll
                for (int ni = 0; ni < 8; ni++)
                    mma_tf32(acc[mi][ni][0], acc[mi][ni][1], acc[mi][ni][2], acc[mi][ni][3],
                             a0, a1, a2, a3, b0[ni], b1[ni]);
            }
        }
    };

    issue_A(0, 0);
    issue_B(0, 0, 0);
    asm volatile("cp.async.commit_group;");

    #pragma unroll 1
    for (int s = 0; s < NS; s++) {
        int abuf = s & 1;
        int sl0 = (3*s) & 3, sl1 = (3*s + 1) & 3, sl2 = (3*s + 2) & 3, sl3 = (3*s + 3) & 3;
        asm volatile("cp.async.wait_group %0;" :: "n"(0) : "memory");
        __syncthreads();
        bool more = (s + 1 < NS);
        issue_B(s, 1, sl1); asm volatile("cp.async.commit_group;");
        issue_B(s, 2, sl2); asm volatile("cp.async.commit_group;");
        if (more) {
            issue_A(s + 1, abuf ^ 1);
            issue_B(s + 1, 0, sl3);
            asm volatile("cp.async.commit_group;");
        }
        compute(abuf, sl0, 0);
        if (more) { asm volatile("cp.async.wait_group %0;" :: "n"(1) : "memory"); }
        else      { asm volatile("cp.async.wait_group %0;" :: "n"(0) : "memory"); }
        __syncthreads();
        compute(abuf, sl1, 1);
        compute(abuf, sl2, 2);
    }
    __syncthreads();

    // ---- epilogue: discard pad rows, add bias, store, fused stats ----
    if (STAGE == 0) { if (tid < 16) sm[tid] = 0.f; }
    else            { if (tid < 256) sm[tid] = 0.f; }
    __syncthreads();

    int cb = wn*64 + rr*2;
    int prow = tile*128 + wm*32 + q;

    float sg[4] = {0.f, 0.f, 0.f, 0.f}, qg[4] = {0.f, 0.f, 0.f, 0.f};

    #pragma unroll
    for (int mi = 0; mi < 2; mi++) {
        #pragma unroll
        for (int half = 0; half < 2; half++) {
            int pp = prow + mi*16 + half*8;
            int zp = pp % PZ; int rem = pp / PZ; int yp = rem % PY; int xp = rem / PY;
            bool valid = (pp < PVOX) && (xp >= 1 && xp <= 32) && (yp >= 1 && yp <= 32)
                         && (zp >= 1 && zp <= 32);
            if (!valid) continue;
            long ob;
            if (STAGE == 0)
                ob = ((long)SLK + (long)b*PVOX + pp) * COUT;
            else
                ob = ((long)b*NVOX + (((xp-1)*RES + (yp-1))*RES + (zp-1))) * COUT;
            float* gout = (STAGE == 0) ? d_gp1 : d_grid2;
            if (STAGE == 0) {
                #pragma unroll
                for (int ni = 0; ni < 8; ni++) {
                    int col = cb + ni*8;
                    float2 o2;
                    o2.x = acc[mi][ni][half*2]   + bias[col];
                    o2.y = acc[mi][ni][half*2+1] + bias[col+1];
                    *(float2*)&gout[ob + col] = o2;
                    int gl = ni >> 1;
                    sg[gl] += o2.x + o2.y;
                    qg[gl] += o2.x*o2.x + o2.y*o2.y;
                }
            } else {
                #pragma unroll
                for (int ni = 0; ni < 8; ni++) {
                    int col = cb + ni*8;
                    float2 o2;
                    o2.x = acc[mi][ni][half*2]   + bias[col];
                    o2.y = acc[mi][ni][half*2+1] + bias[col+1];
                    *(float2*)&gout[ob + col] = o2;
                    acc[mi][ni][half*2]   = o2.x;
                    acc[mi][ni][half*2+1] = o2.y;
                }
            }
        }
    }

    if (STAGE == 0) {
        #pragma unroll
        for (int g = 0; g < 4; g++) {
            #pragma unroll
            for (int off = 16; off > 0; off >>= 1) {
                sg[g] += __shfl_down_sync(0xffffffffu, sg[g], off);
                qg[g] += __shfl_down_sync(0xffffffffu, qg[g], off);
            }
        }
        if (lane == 0) {
            #pragma unroll
            for (int g = 0; g < 4; g++) {
                atomicAdd(&sm[(wn*4 + g)*2 + 0], sg[g]);
                atomicAdd(&sm[(wn*4 + g)*2 + 1], qg[g]);
            }
        }
        __syncthreads();
        if (tid < 16) atomicAdd(&d_gstats1[b*16 + tid], sm[tid]);
    } else {
        #pragma unroll
        for (int ni = 0; ni < 8; ni++) {
            float sx = 0.f, qx = 0.f, sy = 0.f, qy = 0.f;
            #pragma unroll
            for (int mi = 0; mi < 2; mi++) {
                #pragma unroll
                for (int half = 0; half < 2; half++) {
                    int pp = prow + mi*16 + half*8;
                    int zp = pp % PZ; int rem = pp / PZ; int yp = rem % PY; int xp = rem / PY;
                    bool valid = (pp < PVOX) && (xp >= 1 && xp <= 32) && (yp >= 1 && yp <= 32)
                                 && (zp >= 1 && zp <= 32);
                    if (!valid) continue;
                    float vx = acc[mi][ni][half*2], vy = acc[mi][ni][half*2+1];
                    sx += vx; qx += vx*vx; sy += vy; qy += vy*vy;
                }
            }
            #pragma unroll
            for (int off = 4; off <= 16; off <<= 1) {
                sx += __shfl_xor_sync(0xffffffffu, sx, off);
                qx += __shfl_xor_sync(0xffffffffu, qx, off);
                sy += __shfl_xor_sync(0xffffffffu, sy, off);
                qy += __shfl_xor_sync(0xffffffffu, qy, off);
            }
            if (q == 0) {
                int col = cb + ni*8;
                atomicAdd(&sm[col*2 + 0],       sx);
                atomicAdd(&sm[col*2 + 1],       qx);
                atomicAdd(&sm[(col+1)*2 + 0],   sy);
                atomicAdd(&sm[(col+1)*2 + 1],   qy);
            }
        }
        __syncthreads();
        if (tid < 256) atomicAdd(&d_cstats2[b*256 + tid], sm[tid]);
    }
}

// GN1 normalize + swish + rtf32, IN PLACE on gp1 interior
__global__ void k_gn1(const float* __restrict__ g, const float* __restrict__ bt) {
    long i = (long)blockIdx.x * 256 + threadIdx.x;   // BB*NVOX*COUT
    int c = i & 127; int b = (int)(i >> 22);
    int v = (int)((i >> 7) & (NVOX-1));
    int gr = c >> 4;
    float S = d_gstats1[(b*8 + gr)*2], Q = d_gstats1[(b*8 + gr)*2 + 1];
    const float cnt = (float)NVOX * 16.f;
    float mu = S / cnt; float var = Q / cnt - mu*mu;
    float rs = rsqrtf(var + GEPS);
    int x = v >> 10, yy = (v >> 5) & 31, z = v & 31;
    int pp = ((x+1)*PY + (yy+1))*PZ + (z+1);
    long idx = ((long)SLK + (long)b*PVOX + pp)*COUT + c;
    float y = (d_gp1[idx] - mu) * rs * g[c] + bt[c];
    float sw = y / (1.f + expf(-y));
    d_gp1[idx] = rtf32(sw);
}

// ---------------- SE + fold GN2*SE into per-(b,c) affine ---------------------
__global__ void k_se(const float* __restrict__ w1, const float* __restrict__ b1,
                     const float* __restrict__ w2, const float* __restrict__ b2,
                     const float* __restrict__ gamma, const float* __restrict__ beta) {
    int b = blockIdx.x; int c = threadIdx.x;
    __shared__ float s[128], gmu[8], grs[8], s1[16];
    const float cnt = (float)NVOX;
    if (c < 8) {
        float S = 0.f, Q = 0.f;
        for (int j = 0; j < 16; j++) {
            S += d_cstats2[(b*COUT + c*16 + j)*2 + 0];
            Q += d_cstats2[(b*COUT + c*16 + j)*2 + 1];
        }
        float gc = cnt * 16.f;
        float mu = S / gc; float var = Q / gc - mu*mu;
        gmu[c] = mu; grs[c] = rsqrtf(var + GEPS);
    }
    __syncthreads();
    int gr = c >> 4;
    float mu = gmu[gr], rs = grs[gr];
    float csum = d_cstats2[(b*COUT + c)*2];
    s[c] = (csum / cnt - mu) * rs * gamma[c] + beta[c];
    __syncthreads();
    if (c < 16) {
        float a = b1[c];
        for (int j = 0; j < 128; j++) a += w1[c*128 + j] * s[j];
        s1[c] = fmaxf(a, 0.f);
    }
    __syncthreads();
    float a2 = b2[c];
    for (int j = 0; j < 16; j++) a2 += w2[c*16 + j] * s1[j];
    float se = 1.f / (1.f + expf(-a2));
    float rg = rs * gamma[c];
    d_A [b*COUT + c] = rg * se;
    d_Bc[b*COUT + c] = (beta[c] - mu * rg) * se;
}

// ---------------- point branch 1x1 conv + stats --------------------------------
__global__ void k_pt(const float* __restrict__ feat, const float* __restrict__ ptb) {
    int blk = blockIdx.x;
    int b = blk >> 10, n0 = (blk & 1023) * 32;
    __shared__ float fs[CIN*32];
    __shared__ float so[32*COUT];
    __shared__ float ss[256], sq[256];
    for (int e = threadIdx.x; e < CIN*32; e += 256) {
        int ci = e >> 5, nn = e & 31;
        fs[e] = feat[((long)(b*CIN) + ci)*NPTS + n0 + nn];
    }
    __syncthreads();
    int o = threadIdx.x & 127, h = threadIdx.x >> 7;
    float acc[16];
    float bv = ptb[o];
    #pragma unroll
    for (int j = 0; j < 16; j++) acc[j] = bv;
    for (int ci = 0; ci < CIN; ci++) {
        float w = d_ptw[ci*COUT + o];
        #pragma unroll
        for (int j = 0; j < 16; j++)
            acc[j] = fmaf(w, fs[ci*32 + h*16 + j], acc[j]);
    }
    float s = 0.f, q = 0.f;
    #pragma unroll
    for (int j = 0; j < 16; j++) {
        s += acc[j]; q += acc[j]*acc[j];
        so[(h*16 + j)*COUT + o] = acc[j];
    }
    ss[threadIdx.x] = s; sq[threadIdx.x] = q;
    __syncthreads();
    if (threadIdx.x < 8) {
        float S = 0.f, Q = 0.f;
        for (int j = 0; j < 16; j++) {
            int cc = threadIdx.x*16 + j;
            S += ss[cc] + ss[cc+128]; Q += sq[cc] + sq[cc+128];
        }
        atomicAdd(&d_ptstats[(b*8 + threadIdx.x)*2 + 0], S);
        atomicAdd(&d_ptstats[(b*8 + threadIdx.x)*2 + 1], Q);
    }
    for (int e = threadIdx.x; e < 32*COUT; e += 256) {
        int nn = e >> 7, oo = e & 127;
        d_pt[((long)(b*NPTS) + n0 + nn)*COUT + oo] = so[e];
    }
}

__global__ void k_ptab(const float* __restrict__ g, const float* __restrict__ bt) {
    int i = blockIdx.x * 256 + threadIdx.x;
    if (i >= BB*COUT) return;
    int b = i >> 7, c = i & 127, gr = c >> 4;
    const float cnt = 16.f * (float)NPTS;
    float S = d_ptstats[(b*8 + gr)*2], Q = d_ptstats[(b*8 + gr)*2 + 1];
    float mu = S / cnt, var = Q / cnt - mu*mu, rs = rsqrtf(var + GEPS);
    d_ptA[i] = rs * g[c];
    d_ptB[i] = bt[c] - mu * rs * g[c];
}

// ---------------- trilinear devoxelize + point add -> out (coalesced) ---------
__global__ void k_out(float* __restrict__ out) {
    __shared__ float so[64*132];
    int warp = threadIdx.x >> 5, lane = threadIdx.x & 31;
    int blk = blockIdx.x;
    int b = blk >> 9;
    int n0 = (blk & 511) * 64;

    #pragma unroll 1
    for (int pass = 0; pass < 8; pass++) {
        int pt = pass * 8 + warp;
        int n = n0 + pt;
        float nx = d_normc[(b*3+0)*NPTS + n];
        float ny = d_normc[(b*3+1)*NPTS + n];
        float nz = d_normc[(b*3+2)*NPTS + n];
        int lx = (int)floorf(nx); float fx = nx - (float)lx; int hx = min(lx+1, RES-1);
        int ly = (int)floorf(ny); float fy = ny - (float)ly; int hy = min(ly+1, RES-1);
        int lz = (int)floorf(nz); float fz = nz - (float)lz; int hz = min(lz+1, RES-1);

        float4 acc = make_float4(0.f, 0.f, 0.f, 0.f);
        float sumw = 0.f;
        const float4* gp = (const float4*)d_grid2;
        #pragma unroll
        for (int k = 0; k < 8; k++) {
            int dx = k >> 2, dy = (k >> 1) & 1, dz = k & 1;
            int ix = dx ? hx : lx, iy = dy ? hy : ly, iz = dz ? hz : lz;
            float w = (dx ? fx : 1.f - fx) * (dy ? fy : 1.f - fy) * (dz ? fz : 1.f - fz);
            long row = ((long)(b*NVOX) + (ix*RES + iy)*RES + iz) * (COUT/4);
            float4 v = gp[row + lane];
            acc.x += w*v.x; acc.y += w*v.y; acc.z += w*v.z; acc.w += w*v.w;
            sumw += w;
        }
        float4 a  = ((const float4*)d_A )[b*32 + lane];
        float4 bc = ((const float4*)d_Bc)[b*32 + lane];
        float4 gv;
        gv.x = acc.x*a.x + sumw*bc.x; gv.y = acc.y*a.y + sumw*bc.y;
        gv.z = acc.z*a.z + sumw*bc.z; gv.w = acc.w*a.w + sumw*bc.w;

        float4 pv = ((const float4*)d_pt)[((long)(b*NPTS) + n)*32 + lane];
        float4 pa = ((const float4*)d_ptA)[b*32 + lane];
        float4 pb = ((const float4*)d_ptB)[b*32 + lane];
        float y;
        y = pv.x*pa.x + pb.x; gv.x += y / (1.f + expf(-y));
        y = pv.y*pa.y + pb.y; gv.y += y / (1.f + expf(-y));
        y = pv.z*pa.z + pb.z; gv.z += y / (1.f + expf(-y));
        y = pv.w*pa.w + pb.w; gv.w += y / (1.f + expf(-y));

        ((float4*)(so + pt*132))[lane] = gv;
    }
    __syncthreads();
    for (int e = threadIdx.x; e < 64*128; e += 256) {
        int c = e >> 6, n = e & 63;
        out[((long)(b*COUT) + c)*NPTS + n0 + n] = so[n*132 + c];
    }
}

// ---------------- launch --------------------------------------------------------
extern "C" void kernel_launch(void* const* d_in, const int* in_sizes, int n_in,
                              void* d_out, int out_size) {
    const float* features = (const float*)d_in[0];
    const float* coords   = (const float*)d_in[1];
    const float* conv1_w  = (const float*)d_in[2];
    const float* conv1_b  = (const float*)d_in[3];
    const float* gn1_g    = (const float*)d_in[4];
    const float* gn1_b    = (const float*)d_in[5];
    const float* conv2_w  = (const float*)d_in[6];
    const float* conv2_b  = (const float*)d_in[7];
    const float* gn2_g    = (const float*)d_in[8];
    const float* gn2_b    = (const float*)d_in[9];
    const float* se_w1    = (const float*)d_in[10];
    const float* se_b1    = (const float*)d_in[11];
    const float* se_w2    = (const float*)d_in[12];
    const float* se_b2    = (const float*)d_in[13];
    const float* pt_w     = (const float*)d_in[14];
    const float* pt_b     = (const float*)d_in[15];
    const float* ptgn_g   = (const float*)d_in[16];
    const float* ptgn_b   = (const float*)d_in[17];
    float* out = (float*)d_out;

    const int SMEM_B = SMEM_FLOATS * 4;    // 103552
    cudaFuncSetAttribute(k_tconv<CIN,0>,  cudaFuncAttributeMaxDynamicSharedMemorySize, SMEM_B);
    cudaFuncSetAttribute(k_tconv<COUT,1>, cudaFuncAttributeMaxDynamicSharedMemorySize, SMEM_B);

    k_prep<<<(27*4*2048 + 255)/256, 256>>>(conv1_w, conv2_w, pt_w);
    k_zero0<<<(int)(((long)BB*NVOX*CIN)/256), 256>>>();
    k_mean1<<<BB*3*16, 256>>>(coords);
    k_scale1<<<BB*16, 256>>>(coords);
    k_norm<<<(BB*3*NPTS + 255)/256, 256>>>(coords);
    k_scatter<<<BB*(NPTS/32), 256>>>(features);
    k_div<<<(BB*NVOX*CIN)/256, 256>>>();
    k_tconv<CIN,0><<<BB*NTILE, 256, SMEM_B>>>(conv1_b);
    k_gn1<<<(BB*NVOX*COUT)/256, 256>>>(gn1_g, gn1_b);
    k_tconv<COUT,1><<<BB*NTILE, 256, SMEM_B>>>(conv2_b);
    k_se<<<BB, 128>>>(se_w1, se_b1, se_w2, se_b2, gn2_g, gn2_b);
    k_pt<<<BB*(NPTS/32), 256>>>(features, pt_b);
    k_ptab<<<(BB*COUT + 255)/256, 256>>>(ptgn_g, ptgn_b);
    k_out<<<BB*NPTS/64, 256>>>(out);
}

// round 17
// speedup vs baseline: 1.0995x; 1.0470x over previous
#include <cuda_runtime.h>
#include <math.h>
#include <stdint.h>

#define BB 8
#define CIN 64
#define COUT 128
#define NPTS 32768
#define RES 32
#define NVOX (RES*RES*RES)
#define GEPS 1e-5f

#define PX 34
#define PY 34
#define PZ 34
#define PVOX (PX*PY*PZ)          // 39304
#define SLK 2048                 // halo slack rows each side (max reach 1191)
#define NTILE_C 290              // tiles 9..298 (tiles 0-8 & 299-307 are all-pad)
#define TILE_OFF 9

// conv smem partition (floats): KC=32
#define A_STRIDE 36
#define A_BUF (132*A_STRIDE)              // 4752 per buffer
#define B_SLOT 4096                       // one tap shuffled: 128n x 32k
#define SMEM_FLOATS (2*A_BUF + 4*B_SLOT)  // 25888 floats = 103552 B -> 2 CTAs/SM

// ---------------- scratch (static device globals; no allocation) -------------
__device__ float d_msum[BB*3];
__device__ unsigned d_smaxu[BB];
__device__ float d_normc[BB*3*NPTS];
__device__ __align__(16) float d_gp0[((long)BB*PVOX + 2*SLK)*CIN];   // padded tf32 in (conv1)
__device__ __align__(16) float d_gp1[((long)BB*PVOX + 2*SLK)*COUT];  // conv1 out -> gn1 in-place -> conv2 in
__device__ float d_cnt[BB*NVOX];
__device__ float d_grid2[(long)BB*NVOX*COUT];   // compact conv2 out
__device__ float d_pt[(long)BB*NPTS*COUT];      // point branch
// shuffled weights: [tap][ck][nblk(16)][ks(4)][lane(32)] float2 {k, k+4}
__device__ __align__(16) float2 d_wbs1[27*2*16*4*32];   // conv1: NCK=2
__device__ __align__(16) float2 d_wbs2[27*4*16*4*32];   // conv2: NCK=4
__device__ float d_ptw[CIN*COUT];
__device__ float d_gstats1[BB*8*2];
__device__ float d_cstats2[BB*COUT*2];
__device__ float d_ptstats[BB*8*2];
__device__ float d_A[BB*COUT];
__device__ float d_Bc[BB*COUT];
__device__ float d_ptA[BB*COUT];
__device__ float d_ptB[BB*COUT];

// ---------------- helpers -----------------------------------------------------
__device__ __forceinline__ float rtf32(float x) {
    float r; asm("cvt.rna.tf32.f32 %0, %1;" : "=f"(r) : "f"(x)); return r;
}
__device__ __forceinline__ uint32_t smem_u32(const void* p) {
    uint32_t a;
    asm("{ .reg .u64 t; cvta.to.shared.u64 t, %1; cvt.u32.u64 %0, t; }" : "=r"(a) : "l"(p));
    return a;
}
__device__ __forceinline__ void cpa16(uint32_t dst, const void* src) {
    asm volatile("cp.async.cg.shared.global [%0], [%1], 16;" :: "r"(dst), "l"(src));
}
__device__ __forceinline__ void mma_tf32(float& d0, float& d1, float& d2, float& d3,
                                         uint32_t a0, uint32_t a1, uint32_t a2, uint32_t a3,
                                         uint32_t b0, uint32_t b1) {
    asm volatile(
        "mma.sync.aligned.m16n8k8.row.col.f32.tf32.tf32.f32 "
        "{%0,%1,%2,%3}, {%4,%5,%6,%7}, {%8,%9}, {%0,%1,%2,%3};"
        : "+f"(d0), "+f"(d1), "+f"(d2), "+f"(d3)
        : "r"(a0), "r"(a1), "r"(a2), "r"(a3), "r"(b0), "r"(b1));
}

// ---------------- prep: weights -> shuffled fragment layout -------------------
__global__ void k_prep(const float* __restrict__ w1, const float* __restrict__ w2,
                       const float* __restrict__ ptw) {
    int i = blockIdx.x * 256 + threadIdx.x;          // covers 27*4*2048
    int lane = i & 31, ks = (i >> 5) & 3, nblk = (i >> 7) & 15;
    int q = lane >> 2, rr = lane & 3;
    int n = nblk*8 + q;
    if (i < 27*2*2048) {                             // conv1, NCK=2
        int ck = (i >> 11) & 1; int tap = i >> 12;
        int klo = ck*32 + ks*8 + rr;
        d_wbs1[i] = make_float2(rtf32(w1[(n*CIN + klo)*27 + tap]),
                                rtf32(w1[(n*CIN + klo + 4)*27 + tap]));
    }
    if (i < 27*4*2048) {                             // conv2, NCK=4
        int ck = (i >> 11) & 3; int tap = i >> 13;
        int klo = ck*32 + ks*8 + rr;
        d_wbs2[i] = make_float2(rtf32(w2[(n*COUT + klo)*27 + tap]),
                                rtf32(w2[(n*COUT + klo + 4)*27 + tap]));
    }
    if (i < CIN*COUT) {
        int o = i & 127; int ci = i >> 7;
        d_ptw[i] = ptw[o*CIN + ci];
    }
}

// zero only gp0 INTERIOR (pads are statically zero and never written) + small bufs
__global__ void k_zero0() {
    long i = (long)blockIdx.x * 256 + threadIdx.x;   // BB*NVOX*CIN threads
    int c = i & 63; int v = (int)((i >> 6) & (NVOX-1)); int b = (int)(i >> 21);
    int x = v >> 10, y = (v >> 5) & 31, z = v & 31;
    int pp = ((x+1)*PY + (y+1))*PZ + (z+1);
    d_gp0[((long)SLK + (long)b*PVOX + pp)*CIN + c] = 0.f;
    if (i < BB*NVOX)   d_cnt[i] = 0.f;
    if (i < BB*8*2)    d_gstats1[i] = 0.f;
    if (i < BB*COUT*2) d_cstats2[i] = 0.f;
    if (i < BB*8*2)    d_ptstats[i] = 0.f;
    if (i < BB*3)      d_msum[i] = 0.f;
    if (i < BB)        d_smaxu[i] = 0u;
}

// ---------------- voxelize coords ---------------------------------------------
__global__ void k_mean1(const float* __restrict__ coords) {
    int blk = blockIdx.x;
    int chunk = blk & 15; int d = (blk >> 4) % 3; int b = blk / 48;
    __shared__ float s[256];
    float acc = 0.f;
    int base = (b*3 + d)*NPTS + chunk*2048;
    for (int n = threadIdx.x; n < 2048; n += 256) acc += coords[base + n];
    s[threadIdx.x] = acc; __syncthreads();
    for (int o = 128; o > 0; o >>= 1) {
        if (threadIdx.x < o) s[threadIdx.x] += s[threadIdx.x + o];
        __syncthreads();
    }
    if (threadIdx.x == 0) atomicAdd(&d_msum[b*3 + d], s[0]);
}

__global__ void k_scale1(const float* __restrict__ coords) {
    int blk = blockIdx.x;
    int chunk = blk & 15; int b = blk >> 4;
    float mx = d_msum[b*3]   * (1.f/(float)NPTS);
    float my = d_msum[b*3+1] * (1.f/(float)NPTS);
    float mz = d_msum[b*3+2] * (1.f/(float)NPTS);
    __shared__ float s[256];
    float m = 0.f;
    int n0 = chunk*2048;
    for (int n = threadIdx.x; n < 2048; n += 256) {
        float x = coords[(b*3+0)*NPTS + n0 + n] - mx;
        float y = coords[(b*3+1)*NPTS + n0 + n] - my;
        float z = coords[(b*3+2)*NPTS + n0 + n] - mz;
        m = fmaxf(m, sqrtf(x*x + y*y + z*z));
    }
    s[threadIdx.x] = m; __syncthreads();
    for (int o = 128; o > 0; o >>= 1) {
        if (threadIdx.x < o) s[threadIdx.x] = fmaxf(s[threadIdx.x], s[threadIdx.x + o]);
        __syncthreads();
    }
    if (threadIdx.x == 0) atomicMax(&d_smaxu[b], __float_as_uint(s[0]));
}

__global__ void k_norm(const float* __restrict__ coords) {
    int i = blockIdx.x * 256 + threadIdx.x;
    if (i >= BB*3*NPTS) return;
    int b = i / (3*NPTS); int d = (i / NPTS) % 3;
    float mean = d_msum[b*3 + d] * (1.f/(float)NPTS);
    float scale = __uint_as_float(d_smaxu[b]) * 2.f;
    float t = (coords[i] - mean) / scale + 0.5f;
    d_normc[i] = fminf(fmaxf(t * (float)RES, 0.f), (float)(RES - 1));
}

// ---------------- scatter-mean voxelization into padded grid -----------------
// 256 thr / 32 points: stage 64ch x 32pt tile through smem (coalesced reads),
// then each warp scatters 4 points (atomics coalesced as before).
__global__ void k_scatter(const float* __restrict__ feat) {
    __shared__ float fs[CIN*32];           // [c][nn]
    int blk = blockIdx.x;                  // BB*NPTS/32
    int b = blk >> 10, n0 = (blk & 1023) * 32;
    int tid = threadIdx.x, warp = tid >> 5, lane = tid & 31;

    const float* fb = feat + (long)b*CIN*NPTS + n0;
    #pragma unroll
    for (int o2 = 0; o2 < 8; o2++) {
        int e = o2 * 256 + tid;            // e = c*32 + nn
        int c = e >> 5, nn = e & 31;
        fs[e] = fb[(long)c * NPTS + nn];
    }
    __syncthreads();

    #pragma unroll
    for (int j = 0; j < 4; j++) {
        int pt = warp * 4 + j;
        int n = n0 + pt;
        int ix = min(max((int)rintf(d_normc[(b*3+0)*NPTS + n]), 0), RES-1);
        int iy = min(max((int)rintf(d_normc[(b*3+1)*NPTS + n]), 0), RES-1);
        int iz = min(max((int)rintf(d_normc[(b*3+2)*NPTS + n]), 0), RES-1);
        int pp = ((ix+1)*PY + (iy+1))*PZ + (iz+1);
        float* row = d_gp0 + ((long)SLK + (long)b*PVOX + pp) * CIN;
        atomicAdd(&row[lane],      fs[lane*32 + pt]);
        atomicAdd(&row[lane + 32], fs[(lane+32)*32 + pt]);
        if (lane == 0) atomicAdd(&d_cnt[b*NVOX + ((ix*RES + iy)*RES + iz)], 1.f);
    }
}

__global__ void k_div() {
    long i = (long)blockIdx.x * 256 + threadIdx.x;
    int c = i & 63; int v = (int)((i >> 6) & (NVOX-1)); int b = (int)(i >> 21);
    int x = v >> 10, y = (v >> 5) & 31, z = v & 31;
    int pp = ((x+1)*PY + (y+1))*PZ + (z+1);
    float cntv = fmaxf(d_cnt[b*NVOX + v], 1.f);
    float* a = d_gp0 + ((long)SLK + (long)b*PVOX + pp) * CIN + c;
    *a = rtf32(*a / cntv);
}

// ---------------- tf32 mma.sync implicit-GEMM 3x3x3 conv ----------------------
// M=128, 256 thr = 8 warps (4m x 2n), 2 CTAs/SM (103.5 KB smem).
// Tiles 0-8 and 299-307 contain only x-halo pad rows -> skipped entirely
// (grid = BB*290, tile = blk%290 + 9).
// Stage-top holds A(s)+B_t0(s); issue [B_t1][B_t2][A(s+1)+B_t0(s+1)];
// single wait(1) after dz0 drains BOTH B_t1 and B_t2, dz1+dz2 back-to-back.
// STAGE 0: padded gp1 + fused GN1 group stats; STAGE 1: grid2 + channel stats.
template<int CI, int STAGE>
__global__ void __launch_bounds__(256, 2) k_tconv(const float* __restrict__ bias) {
    extern __shared__ float sm[];
    const int NCK = CI / 32;
    const int NS = 9 * NCK;

    const float*  __restrict__ gin = (STAGE == 0) ? (d_gp0 + (long)SLK*CI)
                                                  : (d_gp1 + (long)SLK*CI);
    const float2* __restrict__ wbs = (STAGE == 0) ? d_wbs1 : d_wbs2;

    int blk = blockIdx.x;                   // BB*NTILE_C
    int b = blk / NTILE_C, tile = blk % NTILE_C + TILE_OFF;
    long pbase = (long)b * PVOX + tile * 128;

    int tid = threadIdx.x, warp = tid >> 5, lane = tid & 31;
    int wm = warp & 3, wn = warp >> 2;
    uint32_t smb = smem_u32(sm);
    uint32_t aAu[2] = { smb, smb + A_BUF*4 };
    uint32_t aBbase = smb + 2*A_BUF*4;

    float acc[2][8][4];
    #pragma unroll
    for (int mi = 0; mi < 2; mi++)
        #pragma unroll
        for (int ni = 0; ni < 8; ni++)
            #pragma unroll
            for (int j = 0; j < 4; j++) acc[mi][ni][j] = 0.f;

    int q = lane >> 2, rr = lane & 3;
    int aoffs = (wm*32 + q)*A_STRIDE + rr;
    int boffs2 = (wn*8)*128 + lane;

    auto issue_A = [&](int s, int abuf) {
        int dxy = s / NCK, ck = s - (s / NCK) * NCK;
        int dxx = dxy / 3 - 1, dyy = dxy % 3 - 1;
        long astart = pbase + dxx * (PY*PZ) + dyy * PZ - 1;
        const float* asrc = gin + astart * CI + ck * 32;
        uint32_t aA = aAu[abuf];
        #pragma unroll
        for (int o2 = 0; o2 < 5; o2++) {
            int i = o2 * 256 + tid;
            if (i < 130*8) {
                int r = i >> 3, seg = i & 7;
                cpa16(aA + (uint32_t)(r*(A_STRIDE*4) + seg*16), asrc + (long)r * CI + seg*4);
            }
        }
    };
    auto issue_B = [&](int s, int dz, int slot) {
        int dxy = s / NCK, ck = s - (s / NCK) * NCK;
        int tap = dxy*3 + dz;
        const float2* bsrc = wbs + (long)(tap * NCK + ck) * 2048;
        uint32_t aB = aBbase + (uint32_t)slot * (B_SLOT*4);
        #pragma unroll
        for (int o2 = 0; o2 < 4; o2++) {
            int i = o2 * 256 + tid;
            cpa16(aB + (uint32_t)(i*16), (const char*)bsrc + i*16);
        }
    };
    auto compute = [&](int abuf, int slot, int dz) {
        const uint32_t* sAu = (const uint32_t*)sm + abuf*A_BUF;
        const float2* sB2 = (const float2*)(sm + 2*A_BUF) + slot*(B_SLOT/2);
        int abase0 = aoffs + dz*A_STRIDE;
        #pragma unroll
        for (int ks = 0; ks < 4; ks++) {
            int k0 = ks * 8;
            uint32_t b0[8], b1[8];
            #pragma unroll
            for (int ni = 0; ni < 8; ni++) {
                float2 bv = sB2[boffs2 + ni*128 + ks*32];
                b0[ni] = __float_as_uint(bv.x);
                b1[ni] = __float_as_uint(bv.y);
            }
            #pragma unroll
            for (int mi = 0; mi < 2; mi++) {
                int abase = abase0 + mi*16*A_STRIDE + k0;
                uint32_t a0 = sAu[abase];
                uint32_t a1 = sAu[abase + 8*A_STRIDE];
                uint32_t a2 = sAu[abase + 4];
                uint32_t a3 = sAu[abase + 8*A_STRIDE + 4];
                #pragma unroll
                for (int ni = 0; ni < 8; ni++)
                    mma_tf32(acc[mi][ni][0], acc[mi][ni][1], acc[mi][ni][2], acc[mi][ni][3],
                             a0, a1, a2, a3, b0[ni], b1[ni]);
            }
        }
    };

    issue_A(0, 0);
    issue_B(0, 0, 0);
    asm volatile("cp.async.commit_group;");

    #pragma unroll 1
    for (int s = 0; s < NS; s++) {
        int abuf = s & 1;
        int sl0 = (3*s) & 3, sl1 = (3*s + 1) & 3, sl2 = (3*s + 2) & 3, sl3 = (3*s + 3) & 3;
        asm volatile("cp.async.wait_group %0;" :: "n"(0) : "memory");
        __syncthreads();
        bool more = (s + 1 < NS);
        issue_B(s, 1, sl1); asm volatile("cp.async.commit_group;");
        issue_B(s, 2, sl2); asm volatile("cp.async.commit_group;");
        if (more) {
            issue_A(s + 1, abuf ^ 1);
            issue_B(s + 1, 0, sl3);
            asm volatile("cp.async.commit_group;");
        }
        compute(abuf, sl0, 0);
        if (more) { asm volatile("cp.async.wait_group %0;" :: "n"(1) : "memory"); }
        else      { asm volatile("cp.async.wait_group %0;" :: "n"(0) : "memory"); }
        __syncthreads();
        compute(abuf, sl1, 1);
        compute(abuf, sl2, 2);
    }
    __syncthreads();

    // ---- epilogue: discard pad rows, add bias, store, fused stats ----
    if (STAGE == 0) { if (tid < 16) sm[tid] = 0.f; }
    else            { if (tid < 256) sm[tid] = 0.f; }
    __syncthreads();

    int cb = wn*64 + rr*2;
    int prow = tile*128 + wm*32 + q;

    float sg[4] = {0.f, 0.f, 0.f, 0.f}, qg[4] = {0.f, 0.f, 0.f, 0.f};

    #pragma unroll
    for (int mi = 0; mi < 2; mi++) {
        #pragma unroll
        for (int half = 0; half < 2; half++) {
            int pp = prow + mi*16 + half*8;
            int zp = pp % PZ; int rem = pp / PZ; int yp = rem % PY; int xp = rem / PY;
            bool valid = (pp < PVOX) && (xp >= 1 && xp <= 32) && (yp >= 1 && yp <= 32)
                         && (zp >= 1 && zp <= 32);
            if (!valid) continue;
            long ob;
            if (STAGE == 0)
                ob = ((long)SLK + (long)b*PVOX + pp) * COUT;
            else
                ob = ((long)b*NVOX + (((xp-1)*RES + (yp-1))*RES + (zp-1))) * COUT;
            float* gout = (STAGE == 0) ? d_gp1 : d_grid2;
            if (STAGE == 0) {
                #pragma unroll
                for (int ni = 0; ni < 8; ni++) {
                    int col = cb + ni*8;
                    float2 o2;
                    o2.x = acc[mi][ni][half*2]   + bias[col];
                    o2.y = acc[mi][ni][half*2+1] + bias[col+1];
                    *(float2*)&gout[ob + col] = o2;
                    int gl = ni >> 1;
                    sg[gl] += o2.x + o2.y;
                    qg[gl] += o2.x*o2.x + o2.y*o2.y;
                }
            } else {
                #pragma unroll
                for (int ni = 0; ni < 8; ni++) {
                    int col = cb + ni*8;
                    float2 o2;
                    o2.x = acc[mi][ni][half*2]   + bias[col];
                    o2.y = acc[mi][ni][half*2+1] + bias[col+1];
                    *(float2*)&gout[ob + col] = o2;
                    acc[mi][ni][half*2]   = o2.x;
                    acc[mi][ni][half*2+1] = o2.y;
                }
            }
        }
    }

    if (STAGE == 0) {
        #pragma unroll
        for (int g = 0; g < 4; g++) {
            #pragma unroll
            for (int off = 16; off > 0; off >>= 1) {
                sg[g] += __shfl_down_sync(0xffffffffu, sg[g], off);
                qg[g] += __shfl_down_sync(0xffffffffu, qg[g], off);
            }
        }
        if (lane == 0) {
            #pragma unroll
            for (int g = 0; g < 4; g++) {
                atomicAdd(&sm[(wn*4 + g)*2 + 0], sg[g]);
                atomicAdd(&sm[(wn*4 + g)*2 + 1], qg[g]);
            }
        }
        __syncthreads();
        if (tid < 16) atomicAdd(&d_gstats1[b*16 + tid], sm[tid]);
    } else {
        #pragma unroll
        for (int ni = 0; ni < 8; ni++) {
            float sx = 0.f, qx = 0.f, sy = 0.f, qy = 0.f;
            #pragma unroll
            for (int mi = 0; mi < 2; mi++) {
                #pragma unroll
                for (int half = 0; half < 2; half++) {
                    int pp = prow + mi*16 + half*8;
                    int zp = pp % PZ; int rem = pp / PZ; int yp = rem % PY; int xp = rem / PY;
                    bool valid = (pp < PVOX) && (xp >= 1 && xp <= 32) && (yp >= 1 && yp <= 32)
                                 && (zp >= 1 && zp <= 32);
                    if (!valid) continue;
                    float vx = acc[mi][ni][half*2], vy = acc[mi][ni][half*2+1];
                    sx += vx; qx += vx*vx; sy += vy; qy += vy*vy;
                }
            }
            #pragma unroll
            for (int off = 4; off <= 16; off <<= 1) {
                sx += __shfl_xor_sync(0xffffffffu, sx, off);
                qx += __shfl_xor_sync(0xffffffffu, qx, off);
                sy += __shfl_xor_sync(0xffffffffu, sy, off);
                qy += __shfl_xor_sync(0xffffffffu, qy, off);
            }
            if (q == 0) {
                int col = cb + ni*8;
                atomicAdd(&sm[col*2 + 0],       sx);
                atomicAdd(&sm[col*2 + 1],       qx);
                atomicAdd(&sm[(col+1)*2 + 0],   sy);
                atomicAdd(&sm[(col+1)*2 + 1],   qy);
            }
        }
        __syncthreads();
        if (tid < 256) atomicAdd(&d_cstats2[b*256 + tid], sm[tid]);
    }
}

// GN1 normalize + swish + rtf32, IN PLACE on gp1 interior
__global__ void k_gn1(const float* __restrict__ g, const float* __restrict__ bt) {
    long i = (long)blockIdx.x * 256 + threadIdx.x;   // BB*NVOX*COUT
    int c = i & 127; int b = (int)(i >> 22);
    int v = (int)((i >> 7) & (NVOX-1));
    int gr = c >> 4;
    float S = d_gstats1[(b*8 + gr)*2], Q = d_gstats1[(b*8 + gr)*2 + 1];
    const float cnt = (float)NVOX * 16.f;
    float mu = S / cnt; float var = Q / cnt - mu*mu;
    float rs = rsqrtf(var + GEPS);
    int x = v >> 10, yy = (v >> 5) & 31, z = v & 31;
    int pp = ((x+1)*PY + (yy+1))*PZ + (z+1);
    long idx = ((long)SLK + (long)b*PVOX + pp)*COUT + c;
    float y = (d_gp1[idx] - mu) * rs * g[c] + bt[c];
    float sw = y / (1.f + expf(-y));
    d_gp1[idx] = rtf32(sw);
}

// ---------------- SE + fold GN2*SE into per-(b,c) affine ---------------------
__global__ void k_se(const float* __restrict__ w1, const float* __restrict__ b1,
                     const float* __restrict__ w2, const float* __restrict__ b2,
                     const float* __restrict__ gamma, const float* __restrict__ beta) {
    int b = blockIdx.x; int c = threadIdx.x;
    __shared__ float s[128], gmu[8], grs[8], s1[16];
    const float cnt = (float)NVOX;
    if (c < 8) {
        float S = 0.f, Q = 0.f;
        for (int j = 0; j < 16; j++) {
            S += d_cstats2[(b*COUT + c*16 + j)*2 + 0];
            Q += d_cstats2[(b*COUT + c*16 + j)*2 + 1];
        }
        float gc = cnt * 16.f;
        float mu = S / gc; float var = Q / gc - mu*mu;
        gmu[c] = mu; grs[c] = rsqrtf(var + GEPS);
    }
    __syncthreads();
    int gr = c >> 4;
    float mu = gmu[gr], rs = grs[gr];
    float csum = d_cstats2[(b*COUT + c)*2];
    s[c] = (csum / cnt - mu) * rs * gamma[c] + beta[c];
    __syncthreads();
    if (c < 16) {
        float a = b1[c];
        for (int j = 0; j < 128; j++) a += w1[c*128 + j] * s[j];
        s1[c] = fmaxf(a, 0.f);
    }
    __syncthreads();
    float a2 = b2[c];
    for (int j = 0; j < 16; j++) a2 += w2[c*16 + j] * s1[j];
    float se = 1.f / (1.f + expf(-a2));
    float rg = rs * gamma[c];
    d_A [b*COUT + c] = rg * se;
    d_Bc[b*COUT + c] = (beta[c] - mu * rg) * se;
}

// ---------------- point branch 1x1 conv + stats --------------------------------
__global__ void k_pt(const float* __restrict__ feat, const float* __restrict__ ptb) {
    int blk = blockIdx.x;
    int b = blk >> 10, n0 = (blk & 1023) * 32;
    __shared__ float fs[CIN*32];
    __shared__ float so[32*COUT];
    __shared__ float ss[256], sq[256];
    for (int e = threadIdx.x; e < CIN*32; e += 256) {
        int ci = e >> 5, nn = e & 31;
        fs[e] = feat[((long)(b*CIN) + ci)*NPTS + n0 + nn];
    }
    __syncthreads();
    int o = threadIdx.x & 127, h = threadIdx.x >> 7;
    float acc[16];
    float bv = ptb[o];
    #pragma unroll
    for (int j = 0; j < 16; j++) acc[j] = bv;
    for (int ci = 0; ci < CIN; ci++) {
        float w = d_ptw[ci*COUT + o];
        #pragma unroll
        for (int j = 0; j < 16; j++)
            acc[j] = fmaf(w, fs[ci*32 + h*16 + j], acc[j]);
    }
    float s = 0.f, q = 0.f;
    #pragma unroll
    for (int j = 0; j < 16; j++) {
        s += acc[j]; q += acc[j]*acc[j];
        so[(h*16 + j)*COUT + o] = acc[j];
    }
    ss[threadIdx.x] = s; sq[threadIdx.x] = q;
    __syncthreads();
    if (threadIdx.x < 8) {
        float S = 0.f, Q = 0.f;
        for (int j = 0; j < 16; j++) {
            int cc = threadIdx.x*16 + j;
            S += ss[cc] + ss[cc+128]; Q += sq[cc] + sq[cc+128];
        }
        atomicAdd(&d_ptstats[(b*8 + threadIdx.x)*2 + 0], S);
        atomicAdd(&d_ptstats[(b*8 + threadIdx.x)*2 + 1], Q);
    }
    for (int e = threadIdx.x; e < 32*COUT; e += 256) {
        int nn = e >> 7, oo = e & 127;
        d_pt[((long)(b*NPTS) + n0 + nn)*COUT + oo] = so[e];
    }
}

__global__ void k_ptab(const float* __restrict__ g, const float* __restrict__ bt) {
    int i = blockIdx.x * 256 + threadIdx.x;
    if (i >= BB*COUT) return;
    int b = i >> 7, c = i & 127, gr = c >> 4;
    const float cnt = 16.f * (float)NPTS;
    float S = d_ptstats[(b*8 + gr)*2], Q = d_ptstats[(b*8 + gr)*2 + 1];
    float mu = S / cnt, var = Q / cnt - mu*mu, rs = rsqrtf(var + GEPS);
    d_ptA[i] = rs * g[c];
    d_ptB[i] = bt[c] - mu * rs * g[c];
}

// ---------------- trilinear devoxelize + point add -> out (coalesced) ---------
__global__ void k_out(float* __restrict__ out) {
    __shared__ float so[64*132];
    int warp = threadIdx.x >> 5, lane = threadIdx.x & 31;
    int blk = blockIdx.x;
    int b = blk >> 9;
    int n0 = (blk & 511) * 64;

    #pragma unroll 1
    for (int pass = 0; pass < 8; pass++) {
        int pt = pass * 8 + warp;
        int n = n0 + pt;
        float nx = d_normc[(b*3+0)*NPTS + n];
        float ny = d_normc[(b*3+1)*NPTS + n];
        float nz = d_normc[(b*3+2)*NPTS + n];
        int lx = (int)floorf(nx); float fx = nx - (float)lx; int hx = min(lx+1, RES-1);
        int ly = (int)floorf(ny); float fy = ny - (float)ly; int hy = min(ly+1, RES-1);
        int lz = (int)floorf(nz); float fz = nz - (float)lz; int hz = min(lz+1, RES-1);

        float4 acc = make_float4(0.f, 0.f, 0.f, 0.f);
        float sumw = 0.f;
        const float4* gp = (const float4*)d_grid2;
        #pragma unroll
        for (int k = 0; k < 8; k++) {
            int dx = k >> 2, dy = (k >> 1) & 1, dz = k & 1;
            int ix = dx ? hx : lx, iy = dy ? hy : ly, iz = dz ? hz : lz;
            float w = (dx ? fx : 1.f - fx) * (dy ? fy : 1.f - fy) * (dz ? fz : 1.f - fz);
            long row = ((long)(b*NVOX) + (ix*RES + iy)*RES + iz) * (COUT/4);
            float4 v = gp[row + lane];
            acc.x += w*v.x; acc.y += w*v.y; acc.z += w*v.z; acc.w += w*v.w;
            sumw += w;
        }
        float4 a  = ((const float4*)d_A )[b*32 + lane];
        float4 bc = ((const float4*)d_Bc)[b*32 + lane];
        float4 gv;
        gv.x = acc.x*a.x + sumw*bc.x; gv.y = acc.y*a.y + sumw*bc.y;
        gv.z = acc.z*a.z + sumw*bc.z; gv.w = acc.w*a.w + sumw*bc.w;

        float4 pv = ((const float4*)d_pt)[((long)(b*NPTS) + n)*32 + lane];
        float4 pa = ((const float4*)d_ptA)[b*32 + lane];
        float4 pb = ((const float4*)d_ptB)[b*32 + lane];
        float y;
        y = pv.x*pa.x + pb.x; gv.x += y / (1.f + expf(-y));
        y = pv.y*pa.y + pb.y; gv.y += y / (1.f + expf(-y));
        y = pv.z*pa.z + pb.z; gv.z += y / (1.f + expf(-y));
        y = pv.w*pa.w + pb.w; gv.w += y / (1.f + expf(-y));

        ((float4*)(so + pt*132))[lane] = gv;
    }
    __syncthreads();
    for (int e = threadIdx.x; e < 64*128; e += 256) {
        int c = e >> 6, n = e & 63;
        out[((long)(b*COUT) + c)*NPTS + n0 + n] = so[n*132 + c];
    }
}

// ---------------- launch --------------------------------------------------------
extern "C" void kernel_launch(void* const* d_in, const int* in_sizes, int n_in,
                              void* d_out, int out_size) {
    const float* features = (const float*)d_in[0];
    const float* coords   = (const float*)d_in[1];
    const float* conv1_w  = (const float*)d_in[2];
    const float* conv1_b  = (const float*)d_in[3];
    const float* gn1_g    = (const float*)d_in[4];
    const float* gn1_b    = (const float*)d_in[5];
    const float* conv2_w  = (const float*)d_in[6];
    const float* conv2_b  = (const float*)d_in[7];
    const float* gn2_g    = (const float*)d_in[8];
    const float* gn2_b    = (const float*)d_in[9];
    const float* se_w1    = (const float*)d_in[10];
    const float* se_b1    = (const float*)d_in[11];
    const float* se_w2    = (const float*)d_in[12];
    const float* se_b2    = (const float*)d_in[13];
    const float* pt_w     = (const float*)d_in[14];
    const float* pt_b     = (const float*)d_in[15];
    const float* ptgn_g   = (const float*)d_in[16];
    const float* ptgn_b   = (const float*)d_in[17];
    float* out = (float*)d_out;

    const int SMEM_B = SMEM_FLOATS * 4;    // 103552
    cudaFuncSetAttribute(k_tconv<CIN,0>,  cudaFuncAttributeMaxDynamicSharedMemorySize, SMEM_B);
    cudaFuncSetAttribute(k_tconv<COUT,1>, cudaFuncAttributeMaxDynamicSharedMemorySize, SMEM_B);

    k_prep<<<(27*4*2048 + 255)/256, 256>>>(conv1_w, conv2_w, pt_w);
    k_zero0<<<(int)(((long)BB*NVOX*CIN)/256), 256>>>();
    k_mean1<<<BB*3*16, 256>>>(coords);
    k_scale1<<<BB*16, 256>>>(coords);
    k_norm<<<(BB*3*NPTS + 255)/256, 256>>>(coords);
    k_scatter<<<BB*(NPTS/32), 256>>>(features);
    k_div<<<(BB*NVOX*CIN)/256, 256>>>();
    k_tconv<CIN,0><<<BB*NTILE_C, 256, SMEM_B>>>(conv1_b);
    k_gn1<<<(BB*NVOX*COUT)/256, 256>>>(gn1_g, gn1_b);
    k_tconv<COUT,1><<<BB*NTILE_C, 256, SMEM_B>>>(conv2_b);
    k_se<<<BB, 128>>>(se_w1, se_b1, se_w2, se_b2, gn2_g, gn2_b);
    k_pt<<<BB*(NPTS/32), 256>>>(features, pt_b);
    k_ptab<<<(BB*COUT + 255)/256, 256>>>(ptgn_g, ptgn_b);
    k_out<<<BB*NPTS/64, 256>>>(out);
}